// round 1
// baseline (speedup 1.0000x reference)
#include <cuda_runtime.h>
#include <math.h>
#include <float.h>

#define BATCH 8192
#define DIM   128
#define NCLS  1000
#define TI    128
#define TJ    128
#define NSPLIT 4
#define JT_TOTAL (BATCH / TJ)             /* 64 */
#define JT_PER_SPLIT (JT_TOTAL / NSPLIT)  /* 16 */
#define SMEM_BYTES ((2 * TI * DIM + TJ) * 4 + TJ * 4)

// ---- device scratch (no allocations allowed) ----
__device__ float g_sq[BATCH];
__device__ float g_pv[BATCH * NSPLIT];
__device__ int   g_pi[BATCH * NSPLIT];
__device__ float g_nv[BATCH * NSPLIT];
__device__ int   g_ni[BATCH * NSPLIT];
__device__ float g_ce;
__device__ float g_tri;
__device__ int   g_cnt;

// ---------------------------------------------------------------------------
// prep: zero accumulators + per-row squared norms (warp per row)
// ---------------------------------------------------------------------------
__global__ void prep_kernel(const float* __restrict__ emb) {
    int wid = threadIdx.x >> 5, lane = threadIdx.x & 31;
    int row = blockIdx.x * 8 + wid;
    if (blockIdx.x == 0 && threadIdx.x == 0) { g_ce = 0.f; g_tri = 0.f; g_cnt = 0; }
    float4 v = *reinterpret_cast<const float4*>(emb + (size_t)row * DIM + lane * 4);
    float s = v.x * v.x + v.y * v.y + v.z * v.z + v.w * v.w;
#pragma unroll
    for (int off = 16; off; off >>= 1) s += __shfl_xor_sync(0xffffffffu, s, off);
    if (lane == 0) g_sq[row] = s;
}

// ---------------------------------------------------------------------------
// cross entropy with label smoothing (warp per row, online softmax)
// ---------------------------------------------------------------------------
__global__ void ce_kernel(const float* __restrict__ logits, const int* __restrict__ labels) {
    __shared__ float warp_loss[8];
    int wid = threadIdx.x >> 5, lane = threadIdx.x & 31;
    int row = blockIdx.x * 8 + wid;
    const float* x = logits + (size_t)row * NCLS;
    float m = -FLT_MAX, s = 0.f, sx = 0.f;
    for (int c = lane; c < NCLS; c += 32) {
        float v = __ldg(x + c);
        sx += v;
        float nm = fmaxf(m, v);
        s = s * __expf(m - nm) + __expf(v - nm);
        m = nm;
    }
#pragma unroll
    for (int off = 16; off; off >>= 1) {
        float om = __shfl_xor_sync(0xffffffffu, m, off);
        float os = __shfl_xor_sync(0xffffffffu, s, off);
        float nm = fmaxf(m, om);
        s = s * __expf(m - nm) + os * __expf(om - nm);
        m = nm;
        sx += __shfl_xor_sync(0xffffffffu, sx, off);
    }
    if (lane == 0) {
        float lse = m + logf(s);
        float xl  = __ldg(x + labels[row]);
        warp_loss[wid] = 0.9f * (lse - xl) + 0.1f * (lse - sx * (1.0f / (float)NCLS));
    }
    __syncthreads();
    if (threadIdx.x == 0) {
        float b = 0.f;
#pragma unroll
        for (int w = 0; w < 8; w++) b += warp_loss[w];
        atomicAdd(&g_ce, b);
    }
}

// ---------------------------------------------------------------------------
// fused Gram + batch-hard mining
// 128x128 tile / block, 256 threads, 8x8 micro-tile, k-major swizzled smem
// swizzle: element (r,k) stored at k*128 + (r ^ (((k>>2)&7)<<2))
// keeps float4 LDS aligned+conflict-free; transpose STS at 4-way.
// ---------------------------------------------------------------------------
__global__ __launch_bounds__(256, 1)
void mine_kernel(const float* __restrict__ emb, const int* __restrict__ labels) {
    extern __shared__ float smem[];
    float* sA   = smem;                // TI * DIM (k-major, swizzled)
    float* sB   = smem + TI * DIM;     // TJ * DIM
    float* sq_s = sB + TJ * DIM;       // TJ
    int*   lab_s = (int*)(sq_s + TJ);  // TJ

    const int tid = threadIdx.x;
    const int tx = tid & 15;           // j group
    const int ty = tid >> 4;           // i group
    const int i0 = blockIdx.x * TI;
    const int split = blockIdx.y;

    // load A tile once (transpose + swizzle)
    for (int it = tid; it < TI * (DIM / 4); it += 256) {
        int r = it >> 5, c4 = it & 31;
        float4 v = *reinterpret_cast<const float4*>(emb + (size_t)(i0 + r) * DIM + c4 * 4);
        int f = (c4 & 7) << 2;
        int base = (c4 * 4) * TI + (r ^ f);
        sA[base] = v.x; sA[base + TI] = v.y; sA[base + 2 * TI] = v.z; sA[base + 3 * TI] = v.w;
    }

    int li[8], ig[8];
#pragma unroll
    for (int u = 0; u < 8; u++) { ig[u] = i0 + ty * 8 + u; li[u] = labels[ig[u]]; }

    float pv[8], nv[8]; int pi[8], ni[8];
#pragma unroll
    for (int u = 0; u < 8; u++) { pv[u] = -FLT_MAX; nv[u] = FLT_MAX; pi[u] = 0; ni[u] = 0; }

    for (int jt = split * JT_PER_SPLIT; jt < (split + 1) * JT_PER_SPLIT; jt++) {
        const int j0 = jt * TJ;
        __syncthreads();  // prior iteration done consuming sB/sq_s/lab_s (also covers A load)
        for (int it = tid; it < TJ * (DIM / 4); it += 256) {
            int r = it >> 5, c4 = it & 31;
            float4 v = *reinterpret_cast<const float4*>(emb + (size_t)(j0 + r) * DIM + c4 * 4);
            int f = (c4 & 7) << 2;
            int base = (c4 * 4) * TJ + (r ^ f);
            sB[base] = v.x; sB[base + TJ] = v.y; sB[base + 2 * TJ] = v.z; sB[base + 3 * TJ] = v.w;
        }
        if (tid < TJ) { sq_s[tid] = g_sq[j0 + tid]; lab_s[tid] = labels[j0 + tid]; }
        __syncthreads();

        float acc[8][8];
#pragma unroll
        for (int u = 0; u < 8; u++)
#pragma unroll
            for (int v = 0; v < 8; v++) acc[u][v] = 0.f;

#pragma unroll 2
        for (int k4 = 0; k4 < DIM / 4; k4++) {
            int f = (k4 & 7) << 2;
            int ia0 = (ty * 8) ^ f;
            int ia1 = (ty * 8 + 4) ^ f;
            int jb0 = (tx * 4) ^ f;
            int jb1 = (64 + tx * 4) ^ f;
            const float* pA = sA + k4 * 4 * TI;
            const float* pB = sB + k4 * 4 * TJ;
#pragma unroll
            for (int kk = 0; kk < 4; kk++) {
                float4 a0 = *reinterpret_cast<const float4*>(pA + kk * TI + ia0);
                float4 a1 = *reinterpret_cast<const float4*>(pA + kk * TI + ia1);
                float4 b0 = *reinterpret_cast<const float4*>(pB + kk * TJ + jb0);
                float4 b1 = *reinterpret_cast<const float4*>(pB + kk * TJ + jb1);
                float av[8] = {a0.x, a0.y, a0.z, a0.w, a1.x, a1.y, a1.z, a1.w};
                float bv[8] = {b0.x, b0.y, b0.z, b0.w, b1.x, b1.y, b1.z, b1.w};
#pragma unroll
                for (int u = 0; u < 8; u++)
#pragma unroll
                    for (int v = 0; v < 8; v++)
                        acc[u][v] = fmaf(av[u], bv[v], acc[u][v]);
            }
        }

        // mining update: key = sq_j - 2*dot (ranking identical to d2)
#pragma unroll
        for (int v = 0; v < 8; v++) {
            int jl = (v < 4) ? (tx * 4 + v) : (64 + tx * 4 + (v - 4));
            int jg = j0 + jl;
            float sqj = sq_s[jl];
            int lj = lab_s[jl];
#pragma unroll
            for (int u = 0; u < 8; u++) {
                float key = fmaf(-2.f, acc[u][v], sqj);
                if (lj == li[u]) {
                    if (jg != ig[u] && key > pv[u]) { pv[u] = key; pi[u] = jg; }
                } else {
                    if (key < nv[u]) { nv[u] = key; ni[u] = jg; }
                }
            }
        }
    }

    // reduce across the 16 tx lanes sharing each i-row (xor stays in 16-lane halves)
#pragma unroll
    for (int u = 0; u < 8; u++) {
        float bpv = pv[u]; int bpi = pi[u]; float bnv = nv[u]; int bni = ni[u];
#pragma unroll
        for (int off = 8; off; off >>= 1) {
            float opv = __shfl_xor_sync(0xffffffffu, bpv, off);
            int   opi = __shfl_xor_sync(0xffffffffu, bpi, off);
            float onv = __shfl_xor_sync(0xffffffffu, bnv, off);
            int   oni = __shfl_xor_sync(0xffffffffu, bni, off);
            if (opv > bpv) { bpv = opv; bpi = opi; }
            if (onv < bnv) { bnv = onv; bni = oni; }
        }
        if (tx == 0) {
            int row = i0 + ty * 8 + u;
            g_pv[row * NSPLIT + split] = bpv;
            g_pi[row * NSPLIT + split] = bpi;
            g_nv[row * NSPLIT + split] = bnv;
            g_ni[row * NSPLIT + split] = bni;
        }
    }
}

// ---------------------------------------------------------------------------
// finalize: combine split partials, exact fp32 triplet distances (warp/row)
// ---------------------------------------------------------------------------
__global__ void finalize_kernel(const float* __restrict__ emb) {
    int wid = threadIdx.x >> 5, lane = threadIdx.x & 31;
    int row = blockIdx.x * 8 + wid;
    float bpv = -FLT_MAX, bnv = FLT_MAX; int bpi = 0, bni = 0;
    if (lane == 0) {
#pragma unroll
        for (int s = 0; s < NSPLIT; s++) {
            float v = g_pv[row * NSPLIT + s];
            if (v > bpv) { bpv = v; bpi = g_pi[row * NSPLIT + s]; }
            float w = g_nv[row * NSPLIT + s];
            if (w < bnv) { bnv = w; bni = g_ni[row * NSPLIT + s]; }
        }
    }
    bpv = __shfl_sync(0xffffffffu, bpv, 0);
    bpi = __shfl_sync(0xffffffffu, bpi, 0);
    bnv = __shfl_sync(0xffffffffu, bnv, 0);
    bni = __shfl_sync(0xffffffffu, bni, 0);
    bool valid = (bpv > -FLT_MAX) && (bnv < FLT_MAX);
    if (!valid) return;

    const float eps = 1e-6f;
    float4 a = *reinterpret_cast<const float4*>(emb + (size_t)row * DIM + lane * 4);
    float4 p = *reinterpret_cast<const float4*>(emb + (size_t)bpi * DIM + lane * 4);
    float4 n = *reinterpret_cast<const float4*>(emb + (size_t)bni * DIM + lane * 4);
    float dx = a.x - p.x + eps, dy = a.y - p.y + eps, dz = a.z - p.z + eps, dw = a.w - p.w + eps;
    float sp = dx * dx + dy * dy + dz * dz + dw * dw;
    dx = a.x - n.x + eps; dy = a.y - n.y + eps; dz = a.z - n.z + eps; dw = a.w - n.w + eps;
    float sn = dx * dx + dy * dy + dz * dz + dw * dw;
#pragma unroll
    for (int off = 16; off; off >>= 1) {
        sp += __shfl_xor_sync(0xffffffffu, sp, off);
        sn += __shfl_xor_sync(0xffffffffu, sn, off);
    }
    if (lane == 0) {
        float per = sqrtf(sp) - sqrtf(sn) + 0.5f;
        per = fmaxf(per, 0.f);
        atomicAdd(&g_tri, per);
        atomicAdd(&g_cnt, 1);
    }
}

__global__ void combine_kernel(float* out) {
    float ce = g_ce * (1.0f / (float)BATCH);
    float tri = (g_cnt > 0) ? (g_tri / (float)g_cnt) : 0.f;
    out[0] = ce + tri;
}

// ---------------------------------------------------------------------------
extern "C" void kernel_launch(void* const* d_in, const int* in_sizes, int n_in,
                              void* d_out, int out_size) {
    const float* logits = (const float*)d_in[0];
    const float* emb    = (const float*)d_in[1];
    const int*   labels = (const int*)d_in[2];
    float* out = (float*)d_out;

    cudaFuncSetAttribute(mine_kernel, cudaFuncAttributeMaxDynamicSharedMemorySize, SMEM_BYTES);

    prep_kernel<<<BATCH / 8, 256>>>(emb);
    ce_kernel<<<BATCH / 8, 256>>>(logits, labels);
    dim3 grid(BATCH / TI, NSPLIT);
    mine_kernel<<<grid, 256, SMEM_BYTES>>>(emb, labels);
    finalize_kernel<<<BATCH / 8, 256>>>(emb);
    combine_kernel<<<1, 1>>>(out);
}

// round 3
// speedup vs baseline: 1.4132x; 1.4132x over previous
#include <cuda_runtime.h>
#include <math.h>
#include <float.h>
#include <stdint.h>

#define BATCH 8192
#define DIM   128
#define NCLS  1000
#define NSPLIT 2
#define JT_PER_SPLIT 32
#define LDA 132                     /* padded leading dim (words); 132%32=4 -> conflict-free frags */
#define TILE_WORDS (128 * LDA)      /* 16896 words = 67584 B per tile */
#define SMEM_BYTES (3 * TILE_WORDS * 4 + 512)

// ---- device scratch ----
__device__ float    g_sq[BATCH];
__device__ uint32_t g_packed[BATCH];   // (dot+2 bits & ~0x1FFF) | (8191-j)
__device__ int      g_pi[BATCH];       // hardest positive index (-1 invalid)
__device__ int      g_ni[BATCH];       // hardest negative index
__device__ int      g_ccount[NCLS];
__device__ int      g_coff[NCLS];
__device__ int      g_cfill[NCLS];
__device__ int      g_crows[BATCH];
__device__ int      g_flagrows[512];
__device__ int      g_nflag;
__device__ float    g_ce;
__device__ float    g_tri;
__device__ int      g_cnt;

// ================= helpers =================
__device__ __forceinline__ uint32_t smem_u32(const void* p) {
    uint32_t a;
    asm("{ .reg .u64 t; cvta.to.shared.u64 t, %1; cvt.u32.u64 %0, t; }" : "=r"(a) : "l"(p));
    return a;
}
__device__ __forceinline__ void cp16(void* s, const void* g) {
    uint32_t sa = smem_u32(s);
    asm volatile("cp.async.cg.shared.global [%0], [%1], 16;" :: "r"(sa), "l"(g));
}
__device__ __forceinline__ void cpcommit() { asm volatile("cp.async.commit_group;"); }
template<int N> __device__ __forceinline__ void cpwait() {
    asm volatile("cp.async.wait_group %0;" :: "n"(N));
}
__device__ __forceinline__ void mma8(float* c, const uint32_t* a, const uint32_t* b) {
    asm volatile(
        "mma.sync.aligned.m16n8k8.row.col.f32.tf32.tf32.f32 "
        "{%0,%1,%2,%3}, {%4,%5,%6,%7}, {%8,%9}, {%0,%1,%2,%3};"
        : "+f"(c[0]), "+f"(c[1]), "+f"(c[2]), "+f"(c[3])
        : "r"(a[0]), "r"(a[1]), "r"(a[2]), "r"(a[3]), "r"(b[0]), "r"(b[1]));
}

// ---------------------------------------------------------------------------
__global__ void init_kernel() {
    int i = blockIdx.x * 256 + threadIdx.x;
    if (i < BATCH) g_packed[i] = 0u;
    if (i < NCLS) { g_ccount[i] = 0; g_cfill[i] = 0; }
    if (i == 0) { g_ce = 0.f; g_tri = 0.f; g_cnt = 0; g_nflag = 0; }
}

__global__ void prep_kernel(const float* __restrict__ emb) {
    int wid = threadIdx.x >> 5, lane = threadIdx.x & 31;
    int row = blockIdx.x * 8 + wid;
    float4 v = *reinterpret_cast<const float4*>(emb + (size_t)row * DIM + lane * 4);
    float s = v.x * v.x + v.y * v.y + v.z * v.z + v.w * v.w;
#pragma unroll
    for (int off = 16; off; off >>= 1) s += __shfl_xor_sync(0xffffffffu, s, off);
    if (lane == 0) g_sq[row] = s;
}

// ---------------------------------------------------------------------------
__global__ void ce_kernel(const float* __restrict__ logits, const int* __restrict__ labels) {
    __shared__ float warp_loss[8];
    int wid = threadIdx.x >> 5, lane = threadIdx.x & 31;
    int row = blockIdx.x * 8 + wid;
    const float* x = logits + (size_t)row * NCLS;
    float m = -FLT_MAX, s = 0.f, sx = 0.f;
    for (int c = lane; c < NCLS; c += 32) {
        float v = __ldg(x + c);
        sx += v;
        float nm = fmaxf(m, v);
        s = s * __expf(m - nm) + __expf(v - nm);
        m = nm;
    }
#pragma unroll
    for (int off = 16; off; off >>= 1) {
        float om = __shfl_xor_sync(0xffffffffu, m, off);
        float os = __shfl_xor_sync(0xffffffffu, s, off);
        float nm = fmaxf(m, om);
        s = s * __expf(m - nm) + os * __expf(om - nm);
        m = nm;
        sx += __shfl_xor_sync(0xffffffffu, sx, off);
    }
    if (lane == 0) {
        float lse = m + logf(s);
        float xl  = __ldg(x + labels[row]);
        warp_loss[wid] = 0.9f * (lse - xl) + 0.1f * (lse - sx * (1.0f / (float)NCLS));
    }
    __syncthreads();
    if (threadIdx.x == 0) {
        float b = 0.f;
#pragma unroll
        for (int w = 0; w < 8; w++) b += warp_loss[w];
        atomicAdd(&g_ce, b);
    }
}

// ---------------------------------------------------------------------------
// class grouping for exact positive mining
// ---------------------------------------------------------------------------
__global__ void hist_kernel(const int* __restrict__ labels) {
    int i = blockIdx.x * 256 + threadIdx.x;
    atomicAdd(&g_ccount[labels[i]], 1);
}

__global__ void scan_kernel() {
    __shared__ int tmp[1024];
    int t = threadIdx.x;
    int v = (t < NCLS) ? g_ccount[t] : 0;
    tmp[t] = v;
    __syncthreads();
    for (int o = 1; o < 1024; o <<= 1) {
        int x = (t >= o) ? tmp[t - o] : 0;
        __syncthreads();
        tmp[t] += x;
        __syncthreads();
    }
    if (t < NCLS) g_coff[t] = tmp[t] - v;
}

__global__ void scatter_kernel(const int* __restrict__ labels) {
    int i = blockIdx.x * 256 + threadIdx.x;
    int lab = labels[i];
    int pos = g_coff[lab] + atomicAdd(&g_cfill[lab], 1);
    g_crows[pos] = i;
}

// exact hardest positive: warp per class, farthest same-class = max d2, first idx on tie
__global__ void pos_kernel(const float* __restrict__ emb) {
    int w = (blockIdx.x * blockDim.x + threadIdx.x) >> 5;
    int lane = threadIdx.x & 31;
    if (w >= NCLS) return;
    int off = g_coff[w], cnt = g_ccount[w];
    for (int ai = 0; ai < cnt; ai++) {
        int a = g_crows[off + ai];
        float4 av = *reinterpret_cast<const float4*>(emb + (size_t)a * DIM + lane * 4);
        float sqa = g_sq[a];
        float best = -FLT_MAX; int besti = -1;
        for (int bi = 0; bi < cnt; bi++) {
            if (bi == ai) continue;
            int b = g_crows[off + bi];
            float4 bv = *reinterpret_cast<const float4*>(emb + (size_t)b * DIM + lane * 4);
            float d = av.x * bv.x + av.y * bv.y + av.z * bv.z + av.w * bv.w;
#pragma unroll
            for (int o = 16; o; o >>= 1) d += __shfl_xor_sync(0xffffffffu, d, o);
            float d2 = sqa + g_sq[b] - 2.f * d;
            if (d2 > best || (d2 == best && b < besti)) { best = d2; besti = b; }
        }
        if (lane == 0) g_pi[a] = besti;
    }
}

// ---------------------------------------------------------------------------
// tensor-core Gram + packed max-dot mining (negatives, label-blind)
// ---------------------------------------------------------------------------
template<bool DIAG>
__device__ __forceinline__ void mine_tile(
    const float acc[4][4][4], const uint32_t jc[8], uint32_t run[8],
    int wi, int wj, int lane)
{
#pragma unroll
    for (int mf = 0; mf < 4; mf++) {
#pragma unroll
        for (int nf = 0; nf < 4; nf++) {
#pragma unroll
            for (int e = 0; e < 4; e++) {
                int h = e >> 1, eb = e & 1;
                uint32_t bits = __float_as_uint(acc[mf][nf][e] + 2.0f);
                uint32_t pk = (bits & 0xFFFFE000u) | jc[nf * 2 + eb];
                if (DIAG) {
                    int cl = wj * 32 + nf * 8 + 2 * (lane & 3) + eb;
                    int rl = wi * 64 + mf * 16 + (lane >> 2) + 8 * h;
                    if (cl == rl) pk = 0u;
                }
                int q = mf * 2 + h;
                run[q] = run[q] > pk ? run[q] : pk;
            }
        }
    }
}

__global__ __launch_bounds__(256, 1)
void mine_kernel(const float* __restrict__ emb) {
    extern __shared__ float sm[];
    float* sA  = sm;
    float* sB0 = sm + TILE_WORDS;
    float* sB1 = sm + 2 * TILE_WORDS;
    uint32_t* sred = (uint32_t*)(sm + 3 * TILE_WORDS);

    const int tid = threadIdx.x, lane = tid & 31, wid = tid >> 5;
    const int wi = wid & 1, wj = wid >> 1;
    const int i0 = blockIdx.x * 128;
    const int jt0 = blockIdx.y * JT_PER_SPLIT;

    // group 0: A + B0
#pragma unroll
    for (int i = 0; i < 16; i++) {
        int idx = tid + i * 256, r = idx >> 5, c = idx & 31;
        cp16(&sA[r * LDA + c * 4], emb + (size_t)(i0 + r) * DIM + c * 4);
    }
    {
        int j0 = jt0 * 128;
#pragma unroll
        for (int i = 0; i < 16; i++) {
            int idx = tid + i * 256, r = idx >> 5, c = idx & 31;
            cp16(&sB0[r * LDA + c * 4], emb + (size_t)(j0 + r) * DIM + c * 4);
        }
    }
    cpcommit();
    {   // group 1: B1
        int j1 = (jt0 + 1) * 128;
#pragma unroll
        for (int i = 0; i < 16; i++) {
            int idx = tid + i * 256, r = idx >> 5, c = idx & 31;
            cp16(&sB1[r * LDA + c * 4], emb + (size_t)(j1 + r) * DIM + c * 4);
        }
    }
    cpcommit();

    if (tid < 128) sred[tid] = 0u;

    uint32_t run[8];
#pragma unroll
    for (int q = 0; q < 8; q++) run[q] = 0u;

    for (int t = 0; t < JT_PER_SPLIT; t++) {
        if (t + 1 < JT_PER_SPLIT) cpwait<1>(); else cpwait<0>();
        __syncthreads();
        const uint32_t* bA = (const uint32_t*)sA;
        const uint32_t* bB = (const uint32_t*)((t & 1) ? sB1 : sB0);
        const int j0t = (jt0 + t) * 128;

        float acc[4][4][4];
#pragma unroll
        for (int mf = 0; mf < 4; mf++)
#pragma unroll
            for (int nf = 0; nf < 4; nf++)
#pragma unroll
                for (int e = 0; e < 4; e++) acc[mf][nf][e] = 0.f;

#pragma unroll
        for (int ks = 0; ks < 16; ks++) {
            const int k0 = ks * 8;
            uint32_t a[4][4], b[4][2];
#pragma unroll
            for (int mf = 0; mf < 4; mf++) {
                int r0 = wi * 64 + mf * 16 + (lane >> 2);
                int aw = r0 * LDA + k0 + (lane & 3);
                a[mf][0] = bA[aw];
                a[mf][1] = bA[aw + 8 * LDA];
                a[mf][2] = bA[aw + 4];
                a[mf][3] = bA[aw + 8 * LDA + 4];
            }
#pragma unroll
            for (int nf = 0; nf < 4; nf++) {
                int n0 = wj * 32 + nf * 8 + (lane >> 2);
                int bw = n0 * LDA + k0 + (lane & 3);
                b[nf][0] = bB[bw];
                b[nf][1] = bB[bw + 4];
            }
#pragma unroll
            for (int mf = 0; mf < 4; mf++)
#pragma unroll
                for (int nf = 0; nf < 4; nf++)
                    mma8(acc[mf][nf], a[mf], b[nf]);
        }
        __syncthreads();  // done reading B stage t

        if (t + 2 < JT_PER_SPLIT) {
            float* dst = (t & 1) ? sB1 : sB0;
            int j2 = (jt0 + t + 2) * 128;
#pragma unroll
            for (int i = 0; i < 16; i++) {
                int idx = tid + i * 256, r = idx >> 5, c = idx & 31;
                cp16(&dst[r * LDA + c * 4], emb + (size_t)(j2 + r) * DIM + c * 4);
            }
            cpcommit();
        }

        uint32_t jc[8];
#pragma unroll
        for (int nf = 0; nf < 4; nf++)
#pragma unroll
            for (int eb = 0; eb < 2; eb++)
                jc[nf * 2 + eb] =
                    (uint32_t)(8191 - (j0t + wj * 32 + nf * 8 + 2 * (lane & 3) + eb));

        if (j0t == i0) mine_tile<true>(acc, jc, run, wi, wj, lane);
        else           mine_tile<false>(acc, jc, run, wi, wj, lane);
    }

    // quad reduce (lanes sharing same rows differ only in lane&3)
#pragma unroll
    for (int q = 0; q < 8; q++) {
        uint32_t v = run[q];
        v = max(v, __shfl_xor_sync(0xffffffffu, v, 1));
        v = max(v, __shfl_xor_sync(0xffffffffu, v, 2));
        run[q] = v;
    }
    __syncthreads();
    if ((lane & 3) == 0) {
#pragma unroll
        for (int mf = 0; mf < 4; mf++)
#pragma unroll
            for (int h = 0; h < 2; h++) {
                int rl = wi * 64 + mf * 16 + (lane >> 2) + 8 * h;
                atomicMax(&sred[rl], run[mf * 2 + h]);
            }
    }
    __syncthreads();
    if (tid < 128) atomicMax(&g_packed[i0 + tid], sred[tid]);
}

// ---------------------------------------------------------------------------
// flag rows whose unconstrained winner is same-label; otherwise commit index
// ---------------------------------------------------------------------------
__global__ void flag_kernel(const int* __restrict__ labels) {
    int row = blockIdx.x * 256 + threadIdx.x;
    uint32_t pk = g_packed[row];
    int ni = 8191 - (int)(pk & 0x1FFFu);
    if (labels[ni] == labels[row]) {
        int s = atomicAdd(&g_nflag, 1);
        if (s < 512) g_flagrows[s] = row;
    } else {
        g_ni[row] = ni;
    }
}

// exact rescan for flagged rows: min d2 over different-label js, first idx tie
__global__ void patch_kernel(const float* __restrict__ emb, const int* __restrict__ labels) {
    if ((int)blockIdx.x >= g_nflag) return;
    __shared__ float erow[DIM];
    __shared__ float sval[256];
    __shared__ int   sidx[256];
    int row = g_flagrows[blockIdx.x];
    int li = labels[row];
    int tid = threadIdx.x;
    if (tid < DIM) erow[tid] = emb[(size_t)row * DIM + tid];
    __syncthreads();
    float sqr = g_sq[row];
    float bv = FLT_MAX; int bi = BATCH;
    for (int j = tid; j < BATCH; j += 256) {
        if (labels[j] == li) continue;
        float d = 0.f;
        const float4* ej = reinterpret_cast<const float4*>(emb + (size_t)j * DIM);
#pragma unroll
        for (int k = 0; k < 32; k++) {
            float4 v = ej[k];
            const float4 a = *reinterpret_cast<const float4*>(&erow[k * 4]);
            d += a.x * v.x + a.y * v.y + a.z * v.z + a.w * v.w;
        }
        float d2 = sqr + g_sq[j] - 2.f * d;
        if (d2 < bv || (d2 == bv && j < bi)) { bv = d2; bi = j; }
    }
    sval[tid] = bv; sidx[tid] = bi;
    __syncthreads();
    for (int o = 128; o; o >>= 1) {
        if (tid < o) {
            float ov = sval[tid + o]; int oi = sidx[tid + o];
            if (ov < sval[tid] || (ov == sval[tid] && oi < sidx[tid])) {
                sval[tid] = ov; sidx[tid] = oi;
            }
        }
        __syncthreads();
    }
    if (tid == 0) g_ni[row] = sidx[0];
}

// ---------------------------------------------------------------------------
__global__ void finalize_kernel(const float* __restrict__ emb) {
    __shared__ float s_tri[8];
    __shared__ int   s_cnt[8];
    int wid = threadIdx.x >> 5, lane = threadIdx.x & 31;
    int row = blockIdx.x * 8 + wid;
    int pi = g_pi[row];
    int ni = g_ni[row];
    bool valid = (pi >= 0);
    float per = 0.f;
    if (valid) {
        const float eps = 1e-6f;
        float4 a = *reinterpret_cast<const float4*>(emb + (size_t)row * DIM + lane * 4);
        float4 p = *reinterpret_cast<const float4*>(emb + (size_t)pi * DIM + lane * 4);
        float4 n = *reinterpret_cast<const float4*>(emb + (size_t)ni * DIM + lane * 4);
        float dx = a.x - p.x + eps, dy = a.y - p.y + eps, dz = a.z - p.z + eps, dw = a.w - p.w + eps;
        float sp = dx * dx + dy * dy + dz * dz + dw * dw;
        dx = a.x - n.x + eps; dy = a.y - n.y + eps; dz = a.z - n.z + eps; dw = a.w - n.w + eps;
        float sn = dx * dx + dy * dy + dz * dz + dw * dw;
#pragma unroll
        for (int off = 16; off; off >>= 1) {
            sp += __shfl_xor_sync(0xffffffffu, sp, off);
            sn += __shfl_xor_sync(0xffffffffu, sn, off);
        }
        per = fmaxf(sqrtf(sp) - sqrtf(sn) + 0.5f, 0.f);
    }
    if (lane == 0) { s_tri[wid] = valid ? per : 0.f; s_cnt[wid] = valid ? 1 : 0; }
    __syncthreads();
    if (threadIdx.x == 0) {
        float b = 0.f; int c = 0;
#pragma unroll
        for (int w = 0; w < 8; w++) { b += s_tri[w]; c += s_cnt[w]; }
        atomicAdd(&g_tri, b);
        atomicAdd(&g_cnt, c);
    }
}

__global__ void combine_kernel(float* out) {
    float ce = g_ce * (1.0f / (float)BATCH);
    float tri = (g_cnt > 0) ? (g_tri / (float)g_cnt) : 0.f;
    out[0] = ce + tri;
}

// ---------------------------------------------------------------------------
extern "C" void kernel_launch(void* const* d_in, const int* in_sizes, int n_in,
                              void* d_out, int out_size) {
    const float* logits = (const float*)d_in[0];
    const float* emb    = (const float*)d_in[1];
    const int*   labels = (const int*)d_in[2];
    float* out = (float*)d_out;

    cudaFuncSetAttribute(mine_kernel, cudaFuncAttributeMaxDynamicSharedMemorySize, SMEM_BYTES);

    init_kernel<<<32, 256>>>();
    prep_kernel<<<BATCH / 8, 256>>>(emb);
    ce_kernel<<<BATCH / 8, 256>>>(logits, labels);
    hist_kernel<<<32, 256>>>(labels);
    scan_kernel<<<1, 1024>>>();
    scatter_kernel<<<32, 256>>>(labels);
    pos_kernel<<<125, 256>>>(emb);
    dim3 grid(BATCH / 128, NSPLIT);
    mine_kernel<<<grid, 256, SMEM_BYTES>>>(emb);
    flag_kernel<<<32, 256>>>(labels);
    patch_kernel<<<512, 256>>>(emb, labels);
    finalize_kernel<<<BATCH / 8, 256>>>(emb);
    combine_kernel<<<1, 1>>>(out);
}

// round 4
// speedup vs baseline: 1.6524x; 1.1693x over previous
#include <cuda_runtime.h>
#include <cuda_fp16.h>
#include <math.h>
#include <float.h>
#include <stdint.h>

#define BATCH 8192
#define DIM   128
#define NCLS  1000
#define NSPLIT 4
#define JT_PER_SPLIT 16
#define LDH 136                       /* padded halves per row (272B) */
#define TILEH (128 * LDH)             /* halves per tile = 34816 B    */
#define SMEM_BYTES (3 * TILEH * 2 + 512)

// ---- device scratch ----
__device__ __half   g_embh[BATCH * DIM];
__device__ float    g_sq[BATCH];
__device__ uint32_t g_packed[BATCH];   // (dot+2 bits & ~0x1FFF) | (8191-j)
__device__ int      g_pi[BATCH];
__device__ int      g_ni[BATCH];
__device__ int      g_ccount[NCLS];
__device__ int      g_coff[NCLS];
__device__ int      g_cfill[NCLS];
__device__ int      g_crows[BATCH];
__device__ int      g_flagrows[512];
__device__ int      g_nflag;
__device__ float    g_ce;
__device__ float    g_tri;
__device__ int      g_cnt;

// ================= helpers =================
__device__ __forceinline__ uint32_t smem_u32(const void* p) {
    uint32_t a;
    asm("{ .reg .u64 t; cvta.to.shared.u64 t, %1; cvt.u32.u64 %0, t; }" : "=r"(a) : "l"(p));
    return a;
}
__device__ __forceinline__ void cp16(void* s, const void* g) {
    uint32_t sa = smem_u32(s);
    asm volatile("cp.async.cg.shared.global [%0], [%1], 16;" :: "r"(sa), "l"(g));
}
__device__ __forceinline__ void cpcommit() { asm volatile("cp.async.commit_group;"); }
template<int N> __device__ __forceinline__ void cpwait() {
    asm volatile("cp.async.wait_group %0;" :: "n"(N));
}
__device__ __forceinline__ void mma16(float* c, const uint32_t* a, const uint32_t* b) {
    asm volatile(
        "mma.sync.aligned.m16n8k16.row.col.f32.f16.f16.f32 "
        "{%0,%1,%2,%3}, {%4,%5,%6,%7}, {%8,%9}, {%0,%1,%2,%3};"
        : "+f"(c[0]), "+f"(c[1]), "+f"(c[2]), "+f"(c[3])
        : "r"(a[0]), "r"(a[1]), "r"(a[2]), "r"(a[3]), "r"(b[0]), "r"(b[1]));
}

// ---------------------------------------------------------------------------
__global__ void init_kernel() {
    int i = blockIdx.x * 256 + threadIdx.x;
    if (i < BATCH) g_packed[i] = 0u;
    if (i < NCLS) { g_ccount[i] = 0; g_cfill[i] = 0; }
    if (i == 0) { g_ce = 0.f; g_tri = 0.f; g_cnt = 0; g_nflag = 0; }
}

// prep: sq norms + f32->f16 conversion + class histogram (warp per row)
__global__ void prep_kernel(const float* __restrict__ emb, const int* __restrict__ labels) {
    int wid = threadIdx.x >> 5, lane = threadIdx.x & 31;
    int row = blockIdx.x * 8 + wid;
    float4 v = *reinterpret_cast<const float4*>(emb + (size_t)row * DIM + lane * 4);
    __half2 h01 = __floats2half2_rn(v.x, v.y);
    __half2 h23 = __floats2half2_rn(v.z, v.w);
    uint2 hw = make_uint2(*(uint32_t*)&h01, *(uint32_t*)&h23);
    *reinterpret_cast<uint2*>(&g_embh[(size_t)row * DIM + lane * 4]) = hw;
    float s = v.x * v.x + v.y * v.y + v.z * v.z + v.w * v.w;
#pragma unroll
    for (int off = 16; off; off >>= 1) s += __shfl_xor_sync(0xffffffffu, s, off);
    if (lane == 0) {
        g_sq[row] = s;
        atomicAdd(&g_ccount[labels[row]], 1);
    }
}

// ---------------------------------------------------------------------------
__global__ void ce_kernel(const float* __restrict__ logits, const int* __restrict__ labels) {
    __shared__ float warp_loss[8];
    int wid = threadIdx.x >> 5, lane = threadIdx.x & 31;
    int row = blockIdx.x * 8 + wid;
    const float* x = logits + (size_t)row * NCLS;
    float m = -FLT_MAX, s = 0.f, sx = 0.f;
    for (int c = lane; c < NCLS; c += 32) {
        float v = __ldg(x + c);
        sx += v;
        float nm = fmaxf(m, v);
        s = s * __expf(m - nm) + __expf(v - nm);
        m = nm;
    }
#pragma unroll
    for (int off = 16; off; off >>= 1) {
        float om = __shfl_xor_sync(0xffffffffu, m, off);
        float os = __shfl_xor_sync(0xffffffffu, s, off);
        float nm = fmaxf(m, om);
        s = s * __expf(m - nm) + os * __expf(om - nm);
        m = nm;
        sx += __shfl_xor_sync(0xffffffffu, sx, off);
    }
    if (lane == 0) {
        float lse = m + logf(s);
        float xl  = __ldg(x + labels[row]);
        warp_loss[wid] = 0.9f * (lse - xl) + 0.1f * (lse - sx * (1.0f / (float)NCLS));
    }
    __syncthreads();
    if (threadIdx.x == 0) {
        float b = 0.f;
#pragma unroll
        for (int w = 0; w < 8; w++) b += warp_loss[w];
        atomicAdd(&g_ce, b);
    }
}

// ---------------------------------------------------------------------------
__global__ void scan_kernel() {
    __shared__ int tmp[1024];
    int t = threadIdx.x;
    int v = (t < NCLS) ? g_ccount[t] : 0;
    tmp[t] = v;
    __syncthreads();
    for (int o = 1; o < 1024; o <<= 1) {
        int x = (t >= o) ? tmp[t - o] : 0;
        __syncthreads();
        tmp[t] += x;
        __syncthreads();
    }
    if (t < NCLS) g_coff[t] = tmp[t] - v;
}

__global__ void scatter_kernel(const int* __restrict__ labels) {
    int i = blockIdx.x * 256 + threadIdx.x;
    int lab = labels[i];
    int pos = g_coff[lab] + atomicAdd(&g_cfill[lab], 1);
    g_crows[pos] = i;
}

// exact hardest positive: warp per class
__global__ void pos_kernel(const float* __restrict__ emb) {
    int w = (blockIdx.x * blockDim.x + threadIdx.x) >> 5;
    int lane = threadIdx.x & 31;
    if (w >= NCLS) return;
    int off = g_coff[w], cnt = g_ccount[w];
    for (int ai = 0; ai < cnt; ai++) {
        int a = g_crows[off + ai];
        float4 av = *reinterpret_cast<const float4*>(emb + (size_t)a * DIM + lane * 4);
        float sqa = g_sq[a];
        float best = -FLT_MAX; int besti = -1;
        for (int bi = 0; bi < cnt; bi++) {
            if (bi == ai) continue;
            int b = g_crows[off + bi];
            float4 bv = *reinterpret_cast<const float4*>(emb + (size_t)b * DIM + lane * 4);
            float d = av.x * bv.x + av.y * bv.y + av.z * bv.z + av.w * bv.w;
#pragma unroll
            for (int o = 16; o; o >>= 1) d += __shfl_xor_sync(0xffffffffu, d, o);
            float d2 = sqa + g_sq[b] - 2.f * d;
            if (d2 > best || (d2 == best && b < besti)) { best = d2; besti = b; }
        }
        if (lane == 0) g_pi[a] = besti;
    }
}

// ---------------------------------------------------------------------------
// fp16 tensor-core Gram + packed max-dot mining (negatives, label-blind)
// ---------------------------------------------------------------------------
template<bool DIAG>
__device__ __forceinline__ void mine_tile(
    const float acc[4][4][4], const uint32_t jc[8], uint32_t run[8],
    int wi, int wj, int lane)
{
#pragma unroll
    for (int mf = 0; mf < 4; mf++) {
#pragma unroll
        for (int nf = 0; nf < 4; nf++) {
#pragma unroll
            for (int e = 0; e < 4; e++) {
                int h = e >> 1, eb = e & 1;
                uint32_t bits = __float_as_uint(acc[mf][nf][e] + 2.0f);
                uint32_t pk = (bits & 0xFFFFE000u) | jc[nf * 2 + eb];
                if (DIAG) {
                    int cl = wj * 32 + nf * 8 + 2 * (lane & 3) + eb;
                    int rl = wi * 64 + mf * 16 + (lane >> 2) + 8 * h;
                    if (cl == rl) pk = 0u;
                }
                int q = mf * 2 + h;
                run[q] = run[q] > pk ? run[q] : pk;
            }
        }
    }
}

__global__ __launch_bounds__(256, 2)
void mine_kernel() {
    extern __shared__ __half smh[];
    __half* sA  = smh;
    __half* sB0 = smh + TILEH;
    __half* sB1 = smh + 2 * TILEH;
    uint32_t* sred = (uint32_t*)(smh + 3 * TILEH);

    const int tid = threadIdx.x, lane = tid & 31, wid = tid >> 5;
    const int wi = wid & 1, wj = wid >> 1;
    const int i0 = blockIdx.x * 128;
    const int jt0 = blockIdx.y * JT_PER_SPLIT;

    // group 0: A + B0   (row = 128 halves = 256B = 16 x 16B chunks)
#pragma unroll
    for (int i = 0; i < 8; i++) {
        int idx = tid + i * 256, r = idx >> 4, c = idx & 15;
        cp16(&sA[r * LDH + c * 8], g_embh + (size_t)(i0 + r) * DIM + c * 8);
    }
    {
        int j0 = jt0 * 128;
#pragma unroll
        for (int i = 0; i < 8; i++) {
            int idx = tid + i * 256, r = idx >> 4, c = idx & 15;
            cp16(&sB0[r * LDH + c * 8], g_embh + (size_t)(j0 + r) * DIM + c * 8);
        }
    }
    cpcommit();
    {   // group 1: B1
        int j1 = (jt0 + 1) * 128;
#pragma unroll
        for (int i = 0; i < 8; i++) {
            int idx = tid + i * 256, r = idx >> 4, c = idx & 15;
            cp16(&sB1[r * LDH + c * 8], g_embh + (size_t)(j1 + r) * DIM + c * 8);
        }
    }
    cpcommit();

    if (tid < 128) sred[tid] = 0u;

    uint32_t run[8];
#pragma unroll
    for (int q = 0; q < 8; q++) run[q] = 0u;

    for (int t = 0; t < JT_PER_SPLIT; t++) {
        if (t + 1 < JT_PER_SPLIT) cpwait<1>(); else cpwait<0>();
        __syncthreads();
        const __half* bB = (t & 1) ? sB1 : sB0;
        const int j0t = (jt0 + t) * 128;

        float acc[4][4][4];
#pragma unroll
        for (int mf = 0; mf < 4; mf++)
#pragma unroll
            for (int nf = 0; nf < 4; nf++)
#pragma unroll
                for (int e = 0; e < 4; e++) acc[mf][nf][e] = 0.f;

#pragma unroll
        for (int ks = 0; ks < 8; ks++) {
            const int k0 = ks * 16;
            uint32_t a[4][4], b[4][2];
#pragma unroll
            for (int mf = 0; mf < 4; mf++) {
                int r0 = wi * 64 + mf * 16 + (lane >> 2);
                const __half* pa = sA + r0 * LDH + k0 + 2 * (lane & 3);
                a[mf][0] = *(const uint32_t*)(pa);
                a[mf][1] = *(const uint32_t*)(pa + 8 * LDH);
                a[mf][2] = *(const uint32_t*)(pa + 8);
                a[mf][3] = *(const uint32_t*)(pa + 8 * LDH + 8);
            }
#pragma unroll
            for (int nf = 0; nf < 4; nf++) {
                int n0 = wj * 32 + nf * 8 + (lane >> 2);
                const __half* pb = bB + n0 * LDH + k0 + 2 * (lane & 3);
                b[nf][0] = *(const uint32_t*)(pb);
                b[nf][1] = *(const uint32_t*)(pb + 8);
            }
#pragma unroll
            for (int mf = 0; mf < 4; mf++)
#pragma unroll
                for (int nf = 0; nf < 4; nf++)
                    mma16(acc[mf][nf], a[mf], b[nf]);
        }
        __syncthreads();  // done reading B stage t

        if (t + 2 < JT_PER_SPLIT) {
            __half* dst = (t & 1) ? sB1 : sB0;
            int j2 = (jt0 + t + 2) * 128;
#pragma unroll
            for (int i = 0; i < 8; i++) {
                int idx = tid + i * 256, r = idx >> 4, c = idx & 15;
                cp16(&dst[r * LDH + c * 8], g_embh + (size_t)(j2 + r) * DIM + c * 8);
            }
            cpcommit();
        }

        uint32_t jc[8];
#pragma unroll
        for (int nf = 0; nf < 4; nf++)
#pragma unroll
            for (int eb = 0; eb < 2; eb++)
                jc[nf * 2 + eb] =
                    (uint32_t)(8191 - (j0t + wj * 32 + nf * 8 + 2 * (lane & 3) + eb));

        if (j0t == i0) mine_tile<true>(acc, jc, run, wi, wj, lane);
        else           mine_tile<false>(acc, jc, run, wi, wj, lane);
    }

    // quad reduce (lanes sharing same rows differ only in lane&3)
#pragma unroll
    for (int q = 0; q < 8; q++) {
        uint32_t v = run[q];
        v = max(v, __shfl_xor_sync(0xffffffffu, v, 1));
        v = max(v, __shfl_xor_sync(0xffffffffu, v, 2));
        run[q] = v;
    }
    __syncthreads();
    if ((lane & 3) == 0) {
#pragma unroll
        for (int mf = 0; mf < 4; mf++)
#pragma unroll
            for (int h = 0; h < 2; h++) {
                int rl = wi * 64 + mf * 16 + (lane >> 2) + 8 * h;
                atomicMax(&sred[rl], run[mf * 2 + h]);
            }
    }
    __syncthreads();
    if (tid < 128) atomicMax(&g_packed[i0 + tid], sred[tid]);
}

// ---------------------------------------------------------------------------
__global__ void flag_kernel(const int* __restrict__ labels) {
    int row = blockIdx.x * 256 + threadIdx.x;
    uint32_t pk = g_packed[row];
    int ni = 8191 - (int)(pk & 0x1FFFu);
    if (labels[ni] == labels[row]) {
        int s = atomicAdd(&g_nflag, 1);
        if (s < 512) g_flagrows[s] = row;
    } else {
        g_ni[row] = ni;
    }
}

__global__ void patch_kernel(const float* __restrict__ emb, const int* __restrict__ labels) {
    if ((int)blockIdx.x >= g_nflag) return;
    __shared__ float erow[DIM];
    __shared__ float sval[256];
    __shared__ int   sidx[256];
    int row = g_flagrows[blockIdx.x];
    int li = labels[row];
    int tid = threadIdx.x;
    if (tid < DIM) erow[tid] = emb[(size_t)row * DIM + tid];
    __syncthreads();
    float sqr = g_sq[row];
    float bv = FLT_MAX; int bi = BATCH;
    for (int j = tid; j < BATCH; j += 256) {
        if (labels[j] == li) continue;
        float d = 0.f;
        const float4* ej = reinterpret_cast<const float4*>(emb + (size_t)j * DIM);
#pragma unroll
        for (int k = 0; k < 32; k++) {
            float4 v = ej[k];
            const float4 a = *reinterpret_cast<const float4*>(&erow[k * 4]);
            d += a.x * v.x + a.y * v.y + a.z * v.z + a.w * v.w;
        }
        float d2 = sqr + g_sq[j] - 2.f * d;
        if (d2 < bv || (d2 == bv && j < bi)) { bv = d2; bi = j; }
    }
    sval[tid] = bv; sidx[tid] = bi;
    __syncthreads();
    for (int o = 128; o; o >>= 1) {
        if (tid < o) {
            float ov = sval[tid + o]; int oi = sidx[tid + o];
            if (ov < sval[tid] || (ov == sval[tid] && oi < sidx[tid])) {
                sval[tid] = ov; sidx[tid] = oi;
            }
        }
        __syncthreads();
    }
    if (tid == 0) g_ni[row] = sidx[0];
}

// ---------------------------------------------------------------------------
__global__ void finalize_kernel(const float* __restrict__ emb) {
    __shared__ float s_tri[8];
    __shared__ int   s_cnt[8];
    int wid = threadIdx.x >> 5, lane = threadIdx.x & 31;
    int row = blockIdx.x * 8 + wid;
    int pi = g_pi[row];
    int ni = g_ni[row];
    bool valid = (pi >= 0);
    float per = 0.f;
    if (valid) {
        const float eps = 1e-6f;
        float4 a = *reinterpret_cast<const float4*>(emb + (size_t)row * DIM + lane * 4);
        float4 p = *reinterpret_cast<const float4*>(emb + (size_t)pi * DIM + lane * 4);
        float4 n = *reinterpret_cast<const float4*>(emb + (size_t)ni * DIM + lane * 4);
        float dx = a.x - p.x + eps, dy = a.y - p.y + eps, dz = a.z - p.z + eps, dw = a.w - p.w + eps;
        float sp = dx * dx + dy * dy + dz * dz + dw * dw;
        dx = a.x - n.x + eps; dy = a.y - n.y + eps; dz = a.z - n.z + eps; dw = a.w - n.w + eps;
        float sn = dx * dx + dy * dy + dz * dz + dw * dw;
#pragma unroll
        for (int off = 16; off; off >>= 1) {
            sp += __shfl_xor_sync(0xffffffffu, sp, off);
            sn += __shfl_xor_sync(0xffffffffu, sn, off);
        }
        per = fmaxf(sqrtf(sp) - sqrtf(sn) + 0.5f, 0.f);
    }
    if (lane == 0) { s_tri[wid] = valid ? per : 0.f; s_cnt[wid] = valid ? 1 : 0; }
    __syncthreads();
    if (threadIdx.x == 0) {
        float b = 0.f; int c = 0;
#pragma unroll
        for (int w = 0; w < 8; w++) { b += s_tri[w]; c += s_cnt[w]; }
        atomicAdd(&g_tri, b);
        atomicAdd(&g_cnt, c);
    }
}

__global__ void combine_kernel(float* out) {
    float ce = g_ce * (1.0f / (float)BATCH);
    float tri = (g_cnt > 0) ? (g_tri / (float)g_cnt) : 0.f;
    out[0] = ce + tri;
}

// ---------------------------------------------------------------------------
extern "C" void kernel_launch(void* const* d_in, const int* in_sizes, int n_in,
                              void* d_out, int out_size) {
    const float* logits = (const float*)d_in[0];
    const float* emb    = (const float*)d_in[1];
    const int*   labels = (const int*)d_in[2];
    float* out = (float*)d_out;

    cudaFuncSetAttribute(mine_kernel, cudaFuncAttributeMaxDynamicSharedMemorySize, SMEM_BYTES);

    init_kernel<<<32, 256>>>();
    prep_kernel<<<BATCH / 8, 256>>>(emb, labels);
    ce_kernel<<<BATCH / 8, 256>>>(logits, labels);
    scan_kernel<<<1, 1024>>>();
    scatter_kernel<<<32, 256>>>(labels);
    pos_kernel<<<125, 256>>>(emb);
    dim3 grid(BATCH / 128, NSPLIT);
    mine_kernel<<<grid, 256, SMEM_BYTES>>>();
    flag_kernel<<<32, 256>>>(labels);
    patch_kernel<<<512, 256>>>(emb, labels);
    finalize_kernel<<<BATCH / 8, 256>>>(emb);
    combine_kernel<<<1, 1>>>(out);
}

// round 5
// speedup vs baseline: 1.6977x; 1.0274x over previous
#include <cuda_runtime.h>
#include <cuda_fp16.h>
#include <math.h>
#include <float.h>
#include <stdint.h>

#define BATCH 8192
#define DIM   128
#define NCLS  1000
#define LDH 136                       /* padded halves per row (272B) */
#define TILEH (128 * LDH)             /* halves per tile (34816 B)    */
#define SMEM_BYTES (3 * TILEH * 2)
#define NCTA 296

// ---- device scratch ----
__device__ __half   g_embh[BATCH * DIM];
__device__ float    g_sq[BATCH];
__device__ uint32_t g_packed[BATCH];   // (dot+2 bits & ~0x1FFF) | (8191-idx)
__device__ int      g_pi[BATCH];
__device__ int      g_ni[BATCH];
__device__ int      g_ccount[NCLS];
__device__ int      g_coff[NCLS];
__device__ int      g_cfill[NCLS];
__device__ int      g_crows[BATCH];
__device__ int      g_flagrows[512];
__device__ int      g_nflag;
__device__ float    g_ce;
__device__ float    g_tri;
__device__ int      g_cnt;

// ================= helpers =================
__device__ __forceinline__ uint32_t smem_u32(const void* p) {
    uint32_t a;
    asm("{ .reg .u64 t; cvta.to.shared.u64 t, %1; cvt.u32.u64 %0, t; }" : "=r"(a) : "l"(p));
    return a;
}
__device__ __forceinline__ void cp16(void* s, const void* g) {
    uint32_t sa = smem_u32(s);
    asm volatile("cp.async.cg.shared.global [%0], [%1], 16;" :: "r"(sa), "l"(g));
}
__device__ __forceinline__ void cpcommit() { asm volatile("cp.async.commit_group;"); }
template<int N> __device__ __forceinline__ void cpwait() {
    asm volatile("cp.async.wait_group %0;" :: "n"(N));
}
__device__ __forceinline__ void mma16(float* c, const uint32_t* a, const uint32_t* b) {
    asm volatile(
        "mma.sync.aligned.m16n8k16.row.col.f32.f16.f16.f32 "
        "{%0,%1,%2,%3}, {%4,%5,%6,%7}, {%8,%9}, {%0,%1,%2,%3};"
        : "+f"(c[0]), "+f"(c[1]), "+f"(c[2]), "+f"(c[3])
        : "r"(a[0]), "r"(a[1]), "r"(a[2]), "r"(a[3]), "r"(b[0]), "r"(b[1]));
}

// triangular decode: linear tile id -> (it, jt), jt >= it, strips of length 64-it
__device__ __forceinline__ void dec_tile(int L, int& it, int& jt) {
    int c = 0, r = 0;
#pragma unroll 1
    while (c + (64 - r) <= L) { c += 64 - r; r++; }
    it = r; jt = r + (L - c);
}

// ---------------------------------------------------------------------------
__global__ void init_kernel() {
    int i = blockIdx.x * 256 + threadIdx.x;
    if (i < BATCH) g_packed[i] = 0u;
    if (i < NCLS) { g_ccount[i] = 0; g_cfill[i] = 0; }
    if (i == 0) { g_ce = 0.f; g_tri = 0.f; g_cnt = 0; g_nflag = 0; }
}

// prep: sq norms + f32->f16 conversion + class histogram (warp per row)
__global__ void prep_kernel(const float* __restrict__ emb, const int* __restrict__ labels) {
    int wid = threadIdx.x >> 5, lane = threadIdx.x & 31;
    int row = blockIdx.x * 8 + wid;
    float4 v = *reinterpret_cast<const float4*>(emb + (size_t)row * DIM + lane * 4);
    __half2 h01 = __floats2half2_rn(v.x, v.y);
    __half2 h23 = __floats2half2_rn(v.z, v.w);
    uint2 hw = make_uint2(*(uint32_t*)&h01, *(uint32_t*)&h23);
    *reinterpret_cast<uint2*>(&g_embh[(size_t)row * DIM + lane * 4]) = hw;
    float s = v.x * v.x + v.y * v.y + v.z * v.z + v.w * v.w;
#pragma unroll
    for (int off = 16; off; off >>= 1) s += __shfl_xor_sync(0xffffffffu, s, off);
    if (lane == 0) {
        g_sq[row] = s;
        atomicAdd(&g_ccount[labels[row]], 1);
    }
}

// ---------------------------------------------------------------------------
__global__ void ce_kernel(const float* __restrict__ logits, const int* __restrict__ labels) {
    __shared__ float warp_loss[8];
    int wid = threadIdx.x >> 5, lane = threadIdx.x & 31;
    int row = blockIdx.x * 8 + wid;
    const float* x = logits + (size_t)row * NCLS;
    float m = -FLT_MAX, s = 0.f, sx = 0.f;
    for (int c = lane; c < NCLS; c += 32) {
        float v = __ldg(x + c);
        sx += v;
        float nm = fmaxf(m, v);
        s = s * __expf(m - nm) + __expf(v - nm);
        m = nm;
    }
#pragma unroll
    for (int off = 16; off; off >>= 1) {
        float om = __shfl_xor_sync(0xffffffffu, m, off);
        float os = __shfl_xor_sync(0xffffffffu, s, off);
        float nm = fmaxf(m, om);
        s = s * __expf(m - nm) + os * __expf(om - nm);
        m = nm;
        sx += __shfl_xor_sync(0xffffffffu, sx, off);
    }
    if (lane == 0) {
        float lse = m + logf(s);
        float xl  = __ldg(x + labels[row]);
        warp_loss[wid] = 0.9f * (lse - xl) + 0.1f * (lse - sx * (1.0f / (float)NCLS));
    }
    __syncthreads();
    if (threadIdx.x == 0) {
        float b = 0.f;
#pragma unroll
        for (int w = 0; w < 8; w++) b += warp_loss[w];
        atomicAdd(&g_ce, b);
    }
}

// ---------------------------------------------------------------------------
// fused scan + scatter (single block)
// ---------------------------------------------------------------------------
__global__ void scan_scatter_kernel(const int* __restrict__ labels) {
    __shared__ int tmp[1024];
    int t = threadIdx.x;
    int v = (t < NCLS) ? g_ccount[t] : 0;
    tmp[t] = v;
    __syncthreads();
    for (int o = 1; o < 1024; o <<= 1) {
        int x = (t >= o) ? tmp[t - o] : 0;
        __syncthreads();
        tmp[t] += x;
        __syncthreads();
    }
    if (t < NCLS) g_coff[t] = tmp[t] - v;
    __syncthreads();
    for (int i = t; i < BATCH; i += 1024) {
        int lab = labels[i];
        int pos = g_coff[lab] + atomicAdd(&g_cfill[lab], 1);
        g_crows[pos] = i;
    }
}

// exact hardest positive: warp per class
__global__ void pos_kernel(const float* __restrict__ emb) {
    int w = (blockIdx.x * blockDim.x + threadIdx.x) >> 5;
    int lane = threadIdx.x & 31;
    if (w >= NCLS) return;
    int off = g_coff[w], cnt = g_ccount[w];
    for (int ai = 0; ai < cnt; ai++) {
        int a = g_crows[off + ai];
        float4 av = *reinterpret_cast<const float4*>(emb + (size_t)a * DIM + lane * 4);
        float sqa = g_sq[a];
        float best = -FLT_MAX; int besti = -1;
        for (int bi = 0; bi < cnt; bi++) {
            if (bi == ai) continue;
            int b = g_crows[off + bi];
            float4 bv = *reinterpret_cast<const float4*>(emb + (size_t)b * DIM + lane * 4);
            float d = av.x * bv.x + av.y * bv.y + av.z * bv.z + av.w * bv.w;
#pragma unroll
        for (int o = 16; o; o >>= 1) d += __shfl_xor_sync(0xffffffffu, d, o);
            float d2 = sqa + g_sq[b] - 2.f * d;
            if (d2 > best || (d2 == best && b < besti)) { best = d2; besti = b; }
        }
        if (lane == 0) g_pi[a] = besti;
    }
}

// ---------------------------------------------------------------------------
// symmetric fp16 tensor-core Gram + bidirectional packed max-dot mining
// ---------------------------------------------------------------------------
template<bool DIAG>
__device__ __forceinline__ void mine_rows(
    const float acc[4][4][4], const uint32_t jc[8], uint32_t run[8],
    int wi, int wj, int lane)
{
#pragma unroll
    for (int mf = 0; mf < 4; mf++) {
#pragma unroll
        for (int nf = 0; nf < 4; nf++) {
#pragma unroll
            for (int e = 0; e < 4; e++) {
                int h = e >> 1, eb = e & 1;
                uint32_t bits = __float_as_uint(acc[mf][nf][e] + 2.0f);
                uint32_t pk = (bits & 0xFFFFE000u) | jc[nf * 2 + eb];
                if (DIAG) {
                    int cl = wj * 32 + nf * 8 + 2 * (lane & 3) + eb;
                    int rl = wi * 64 + mf * 16 + (lane >> 2) + 8 * h;
                    if (cl == rl) pk = 0u;
                }
                int q = mf * 2 + h;
                run[q] = run[q] > pk ? run[q] : pk;
            }
        }
    }
}

__device__ __forceinline__ void mine_cols(
    const float acc[4][4][4], int it, int jt, int wi, int wj, int lane)
{
    uint32_t colrun[8];
#pragma unroll
    for (int q = 0; q < 8; q++) colrun[q] = 0u;
    uint32_t ic[8];
#pragma unroll
    for (int mf = 0; mf < 4; mf++)
#pragma unroll
        for (int h = 0; h < 2; h++)
            ic[mf * 2 + h] =
                (uint32_t)(8191 - (it * 128 + wi * 64 + mf * 16 + (lane >> 2) + 8 * h));
#pragma unroll
    for (int mf = 0; mf < 4; mf++)
#pragma unroll
        for (int nf = 0; nf < 4; nf++)
#pragma unroll
            for (int e = 0; e < 4; e++) {
                int h = e >> 1, eb = e & 1;
                uint32_t bits = __float_as_uint(acc[mf][nf][e] + 2.0f);
                uint32_t pk = (bits & 0xFFFFE000u) | ic[mf * 2 + h];
                int q = nf * 2 + eb;
                colrun[q] = colrun[q] > pk ? colrun[q] : pk;
            }
    // combine the 8 row-groups (lanes differing in bits 2..4)
#pragma unroll
    for (int q = 0; q < 8; q++) {
        uint32_t v = colrun[q];
        v = max(v, __shfl_xor_sync(0xffffffffu, v, 4));
        v = max(v, __shfl_xor_sync(0xffffffffu, v, 8));
        v = max(v, __shfl_xor_sync(0xffffffffu, v, 16));
        colrun[q] = v;
    }
    if ((lane >> 2) == 0) {
#pragma unroll
        for (int nf = 0; nf < 4; nf++)
#pragma unroll
            for (int eb = 0; eb < 2; eb++) {
                int col = jt * 128 + wj * 32 + nf * 8 + 2 * lane + eb;
                atomicMax(&g_packed[col], colrun[nf * 2 + eb]);
            }
    }
}

__device__ __forceinline__ void flush_rows(uint32_t run[8], int it, int wi, int lane) {
#pragma unroll
    for (int q = 0; q < 8; q++) {
        uint32_t v = run[q];
        v = max(v, __shfl_xor_sync(0xffffffffu, v, 1));
        v = max(v, __shfl_xor_sync(0xffffffffu, v, 2));
        run[q] = v;
    }
    if ((lane & 3) == 0) {
#pragma unroll
        for (int mf = 0; mf < 4; mf++)
#pragma unroll
            for (int h = 0; h < 2; h++) {
                int row = it * 128 + wi * 64 + mf * 16 + (lane >> 2) + 8 * h;
                atomicMax(&g_packed[row], run[mf * 2 + h]);
            }
    }
}

__global__ __launch_bounds__(256, 2)
void mine_kernel() {
    extern __shared__ __half smh[];
    __half* sA = smh;
    __half* sB[2] = { smh + TILEH, smh + 2 * TILEH };

    const int tid = threadIdx.x, lane = tid & 31, wid = tid >> 5;
    const int wi = wid & 1, wj = wid >> 1;
    const int k = blockIdx.x;
    const int start = 7 * k + (k < 8 ? k : 8);
    const int cnt = 7 + (k < 8 ? 1 : 0);

    auto loadA = [&](int it) {
#pragma unroll
        for (int i = 0; i < 8; i++) {
            int idx = tid + i * 256, r = idx >> 4, c = idx & 15;
            cp16(&sA[r * LDH + c * 8], g_embh + (size_t)(it * 128 + r) * DIM + c * 8);
        }
    };
    auto loadB = [&](__half* dst, int jt) {
#pragma unroll
        for (int i = 0; i < 8; i++) {
            int idx = tid + i * 256, r = idx >> 4, c = idx & 15;
            cp16(&dst[r * LDH + c * 8], g_embh + (size_t)(jt * 128 + r) * DIM + c * 8);
        }
    };

    int it0, jt0;
    dec_tile(start, it0, jt0);
    loadA(it0); loadB(sB[0], jt0);
    cpcommit();                        // group0: A + B(0)
    if (cnt > 1) { int i1, j1; dec_tile(start + 1, i1, j1); loadB(sB[1], j1); }
    cpcommit();                        // group1: B(1) (possibly empty)

    int cur_it = it0;
    uint32_t run[8];
#pragma unroll
    for (int q = 0; q < 8; q++) run[q] = 0u;

    for (int s = 0; s < cnt; s++) {
        int it, jt;
        dec_tile(start + s, it, jt);
        if (it != cur_it) {
            flush_rows(run, cur_it, wi, lane);
#pragma unroll
            for (int q = 0; q < 8; q++) run[q] = 0u;
            cpwait<0>(); __syncthreads();
            loadA(it); cpcommit();
            cpwait<0>(); __syncthreads();
            cur_it = it;
        } else {
            cpwait<1>(); __syncthreads();
        }
        const __half* bB = sB[s & 1];

        float acc[4][4][4];
#pragma unroll
        for (int mf = 0; mf < 4; mf++)
#pragma unroll
            for (int nf = 0; nf < 4; nf++)
#pragma unroll
                for (int e = 0; e < 4; e++) acc[mf][nf][e] = 0.f;

#pragma unroll
        for (int ks = 0; ks < 8; ks++) {
            const int k0 = ks * 16;
            uint32_t a[4][4], b[4][2];
#pragma unroll
            for (int mf = 0; mf < 4; mf++) {
                int r0 = wi * 64 + mf * 16 + (lane >> 2);
                const __half* pa = sA + r0 * LDH + k0 + 2 * (lane & 3);
                a[mf][0] = *(const uint32_t*)(pa);
                a[mf][1] = *(const uint32_t*)(pa + 8 * LDH);
                a[mf][2] = *(const uint32_t*)(pa + 8);
                a[mf][3] = *(const uint32_t*)(pa + 8 * LDH + 8);
            }
#pragma unroll
            for (int nf = 0; nf < 4; nf++) {
                int n0 = wj * 32 + nf * 8 + (lane >> 2);
                const __half* pb = bB + n0 * LDH + k0 + 2 * (lane & 3);
                b[nf][0] = *(const uint32_t*)(pb);
                b[nf][1] = *(const uint32_t*)(pb + 8);
            }
#pragma unroll
            for (int mf = 0; mf < 4; mf++)
#pragma unroll
                for (int nf = 0; nf < 4; nf++)
                    mma16(acc[mf][nf], a[mf], b[nf]);
        }
        __syncthreads();  // done reading B stage s

        if (s + 2 < cnt) {
            int i2, j2;
            dec_tile(start + s + 2, i2, j2);
            loadB(sB[s & 1], j2);
            cpcommit();
        }

        uint32_t jc[8];
#pragma unroll
        for (int nf = 0; nf < 4; nf++)
#pragma unroll
            for (int eb = 0; eb < 2; eb++)
                jc[nf * 2 + eb] =
                    (uint32_t)(8191 - (jt * 128 + wj * 32 + nf * 8 + 2 * (lane & 3) + eb));

        if (it == jt) {
            mine_rows<true>(acc, jc, run, wi, wj, lane);
        } else {
            mine_rows<false>(acc, jc, run, wi, wj, lane);
            mine_cols(acc, it, jt, wi, wj, lane);
        }
    }
    flush_rows(run, cur_it, wi, lane);
}

// ---------------------------------------------------------------------------
__global__ void flag_kernel(const int* __restrict__ labels) {
    int row = blockIdx.x * 256 + threadIdx.x;
    uint32_t pk = g_packed[row];
    int ni = 8191 - (int)(pk & 0x1FFFu);
    if (labels[ni] == labels[row]) {
        int s = atomicAdd(&g_nflag, 1);
        if (s < 512) g_flagrows[s] = row;
    } else {
        g_ni[row] = ni;
    }
}

__global__ void patch_kernel(const float* __restrict__ emb, const int* __restrict__ labels) {
    if ((int)blockIdx.x >= g_nflag) return;
    __shared__ float erow[DIM];
    __shared__ float sval[256];
    __shared__ int   sidx[256];
    int row = g_flagrows[blockIdx.x];
    int li = labels[row];
    int tid = threadIdx.x;
    if (tid < DIM) erow[tid] = emb[(size_t)row * DIM + tid];
    __syncthreads();
    float sqr = g_sq[row];
    float bv = FLT_MAX; int bi = BATCH;
    for (int j = tid; j < BATCH; j += 256) {
        if (labels[j] == li) continue;
        float d = 0.f;
        const float4* ej = reinterpret_cast<const float4*>(emb + (size_t)j * DIM);
#pragma unroll
        for (int kk = 0; kk < 32; kk++) {
            float4 v = ej[kk];
            const float4 a = *reinterpret_cast<const float4*>(&erow[kk * 4]);
            d += a.x * v.x + a.y * v.y + a.z * v.z + a.w * v.w;
        }
        float d2 = sqr + g_sq[j] - 2.f * d;
        if (d2 < bv || (d2 == bv && j < bi)) { bv = d2; bi = j; }
    }
    sval[tid] = bv; sidx[tid] = bi;
    __syncthreads();
    for (int o = 128; o; o >>= 1) {
        if (tid < o) {
            float ov = sval[tid + o]; int oi = sidx[tid + o];
            if (ov < sval[tid] || (ov == sval[tid] && oi < sidx[tid])) {
                sval[tid] = ov; sidx[tid] = oi;
            }
        }
        __syncthreads();
    }
    if (tid == 0) g_ni[row] = sidx[0];
}

// ---------------------------------------------------------------------------
__global__ void finalize_kernel(const float* __restrict__ emb) {
    __shared__ float s_tri[8];
    __shared__ int   s_cnt[8];
    int wid = threadIdx.x >> 5, lane = threadIdx.x & 31;
    int row = blockIdx.x * 8 + wid;
    int pi = g_pi[row];
    int ni = g_ni[row];
    bool valid = (pi >= 0);
    float per = 0.f;
    if (valid) {
        const float eps = 1e-6f;
        float4 a = *reinterpret_cast<const float4*>(emb + (size_t)row * DIM + lane * 4);
        float4 p = *reinterpret_cast<const float4*>(emb + (size_t)pi * DIM + lane * 4);
        float4 n = *reinterpret_cast<const float4*>(emb + (size_t)ni * DIM + lane * 4);
        float dx = a.x - p.x + eps, dy = a.y - p.y + eps, dz = a.z - p.z + eps, dw = a.w - p.w + eps;
        float sp = dx * dx + dy * dy + dz * dz + dw * dw;
        dx = a.x - n.x + eps; dy = a.y - n.y + eps; dz = a.z - n.z + eps; dw = a.w - n.w + eps;
        float sn = dx * dx + dy * dy + dz * dz + dw * dw;
#pragma unroll
        for (int off = 16; off; off >>= 1) {
            sp += __shfl_xor_sync(0xffffffffu, sp, off);
            sn += __shfl_xor_sync(0xffffffffu, sn, off);
        }
        per = fmaxf(sqrtf(sp) - sqrtf(sn) + 0.5f, 0.f);
    }
    if (lane == 0) { s_tri[wid] = valid ? per : 0.f; s_cnt[wid] = valid ? 1 : 0; }
    __syncthreads();
    if (threadIdx.x == 0) {
        float b = 0.f; int c = 0;
#pragma unroll
        for (int w = 0; w < 8; w++) { b += s_tri[w]; c += s_cnt[w]; }
        atomicAdd(&g_tri, b);
        atomicAdd(&g_cnt, c);
    }
}

__global__ void combine_kernel(float* out) {
    float ce = g_ce * (1.0f / (float)BATCH);
    float tri = (g_cnt > 0) ? (g_tri / (float)g_cnt) : 0.f;
    out[0] = ce + tri;
}

// ---------------------------------------------------------------------------
extern "C" void kernel_launch(void* const* d_in, const int* in_sizes, int n_in,
                              void* d_out, int out_size) {
    const float* logits = (const float*)d_in[0];
    const float* emb    = (const float*)d_in[1];
    const int*   labels = (const int*)d_in[2];
    float* out = (float*)d_out;

    cudaFuncSetAttribute(mine_kernel, cudaFuncAttributeMaxDynamicSharedMemorySize, SMEM_BYTES);

    init_kernel<<<32, 256>>>();
    prep_kernel<<<BATCH / 8, 256>>>(emb, labels);
    ce_kernel<<<BATCH / 8, 256>>>(logits, labels);
    scan_scatter_kernel<<<1, 1024>>>(labels);
    pos_kernel<<<125, 256>>>(emb);
    mine_kernel<<<NCTA, 256, SMEM_BYTES>>>();
    flag_kernel<<<32, 256>>>(labels);
    patch_kernel<<<512, 256>>>(emb, labels);
    finalize_kernel<<<BATCH / 8, 256>>>(emb);
    combine_kernel<<<1, 1>>>(out);
}

// round 6
// speedup vs baseline: 2.1364x; 1.2584x over previous
#include <cuda_runtime.h>
#include <cuda_fp16.h>
#include <math.h>
#include <float.h>
#include <stdint.h>

#define BATCH 8192
#define DIM   128
#define NCLS  1000
#define LDH 136                       /* padded halves per row (272B) */
#define TILEH (128 * LDH)             /* halves per tile (34816 B)    */
#define SMEM_BYTES (3 * TILEH * 2)
#define NCTA 296

// ---- device scratch ----
__device__ __half   g_embh[BATCH * DIM];
__device__ float    g_sq[BATCH];
__device__ uint32_t g_packed[BATCH];   // (dot+2 bits & ~0x1FFF) | (8191-idx)
__device__ int      g_pi[BATCH];
__device__ int      g_ni[BATCH];
__device__ int      g_ccount[NCLS];
__device__ int      g_coff[NCLS];
__device__ int      g_cfill[NCLS];
__device__ int      g_crows[BATCH];
__device__ int      g_flagrows[512];
__device__ int      g_nflag;
__device__ float    g_ce;
__device__ float    g_tri;
__device__ int      g_cnt;

// ================= helpers =================
__device__ __forceinline__ uint32_t smem_u32(const void* p) {
    uint32_t a;
    asm("{ .reg .u64 t; cvta.to.shared.u64 t, %1; cvt.u32.u64 %0, t; }" : "=r"(a) : "l"(p));
    return a;
}
__device__ __forceinline__ void cp16(void* s, const void* g) {
    uint32_t sa = smem_u32(s);
    asm volatile("cp.async.cg.shared.global [%0], [%1], 16;" :: "r"(sa), "l"(g));
}
__device__ __forceinline__ void cpcommit() { asm volatile("cp.async.commit_group;"); }
template<int N> __device__ __forceinline__ void cpwait() {
    asm volatile("cp.async.wait_group %0;" :: "n"(N));
}
__device__ __forceinline__ void mma16(float* c, const uint32_t* a, const uint32_t* b) {
    asm volatile(
        "mma.sync.aligned.m16n8k16.row.col.f32.f16.f16.f32 "
        "{%0,%1,%2,%3}, {%4,%5,%6,%7}, {%8,%9}, {%0,%1,%2,%3};"
        : "+f"(c[0]), "+f"(c[1]), "+f"(c[2]), "+f"(c[3])
        : "r"(a[0]), "r"(a[1]), "r"(a[2]), "r"(a[3]), "r"(b[0]), "r"(b[1]));
}

// triangular decode: linear tile id -> (it, jt), jt >= it, strips of length 64-it
__device__ __forceinline__ void dec_tile(int L, int& it, int& jt) {
    int c = 0, r = 0;
#pragma unroll 1
    while (c + (64 - r) <= L) { c += 64 - r; r++; }
    it = r; jt = r + (L - c);
}

// ---------------------------------------------------------------------------
__global__ void init_kernel() {
    int i = blockIdx.x * 256 + threadIdx.x;
    if (i < BATCH) g_packed[i] = 0u;
    if (i < NCLS) { g_ccount[i] = 0; g_cfill[i] = 0; }
    if (i == 0) { g_ce = 0.f; g_tri = 0.f; g_cnt = 0; g_nflag = 0; }
}

// prep: sq norms + f32->f16 conversion + class histogram (warp per row)
__global__ void prep_kernel(const float* __restrict__ emb, const int* __restrict__ labels) {
    int wid = threadIdx.x >> 5, lane = threadIdx.x & 31;
    int row = blockIdx.x * 8 + wid;
    float4 v = *reinterpret_cast<const float4*>(emb + (size_t)row * DIM + lane * 4);
    __half2 h01 = __floats2half2_rn(v.x, v.y);
    __half2 h23 = __floats2half2_rn(v.z, v.w);
    uint2 hw = make_uint2(*(uint32_t*)&h01, *(uint32_t*)&h23);
    *reinterpret_cast<uint2*>(&g_embh[(size_t)row * DIM + lane * 4]) = hw;
    float s = v.x * v.x + v.y * v.y + v.z * v.z + v.w * v.w;
#pragma unroll
    for (int off = 16; off; off >>= 1) s += __shfl_xor_sync(0xffffffffu, s, off);
    if (lane == 0) {
        g_sq[row] = s;
        atomicAdd(&g_ccount[labels[row]], 1);
    }
}

// ---------------------------------------------------------------------------
// cross entropy, float4 loads (1000 = 250 vec4)
// ---------------------------------------------------------------------------
__global__ void ce_kernel(const float* __restrict__ logits, const int* __restrict__ labels) {
    __shared__ float warp_loss[8];
    int wid = threadIdx.x >> 5, lane = threadIdx.x & 31;
    int row = blockIdx.x * 8 + wid;
    const float* x = logits + (size_t)row * NCLS;
    float m = -FLT_MAX, s = 0.f, sx = 0.f;
#pragma unroll
    for (int i = 0; i < 8; i++) {
        int c4 = lane + 32 * i;
        if (c4 < 250) {
            float4 v = __ldg(reinterpret_cast<const float4*>(x) + c4);
            sx += v.x + v.y + v.z + v.w;
            float ml = fmaxf(fmaxf(v.x, v.y), fmaxf(v.z, v.w));
            float sl = __expf(v.x - ml) + __expf(v.y - ml) +
                       __expf(v.z - ml) + __expf(v.w - ml);
            float nm = fmaxf(m, ml);
            s = s * __expf(m - nm) + sl * __expf(ml - nm);
            m = nm;
        }
    }
#pragma unroll
    for (int off = 16; off; off >>= 1) {
        float om = __shfl_xor_sync(0xffffffffu, m, off);
        float os = __shfl_xor_sync(0xffffffffu, s, off);
        float nm = fmaxf(m, om);
        s = s * __expf(m - nm) + os * __expf(om - nm);
        m = nm;
        sx += __shfl_xor_sync(0xffffffffu, sx, off);
    }
    if (lane == 0) {
        float lse = m + logf(s);
        float xl  = __ldg(x + labels[row]);
        warp_loss[wid] = 0.9f * (lse - xl) + 0.1f * (lse - sx * (1.0f / (float)NCLS));
    }
    __syncthreads();
    if (threadIdx.x == 0) {
        float b = 0.f;
#pragma unroll
        for (int w = 0; w < 8; w++) b += warp_loss[w];
        atomicAdd(&g_ce, b);
    }
}

// ---------------------------------------------------------------------------
// fused scan + scatter (single block, warp-shuffle scan)
// ---------------------------------------------------------------------------
__global__ void scan_scatter_kernel(const int* __restrict__ labels) {
    __shared__ int wsum[32];
    int t = threadIdx.x, lane = t & 31, w = t >> 5;
    int v = (t < NCLS) ? g_ccount[t] : 0;
    int x = v;
#pragma unroll
    for (int o = 1; o < 32; o <<= 1) {
        int y = __shfl_up_sync(0xffffffffu, x, o);
        if (lane >= o) x += y;
    }
    if (lane == 31) wsum[w] = x;
    __syncthreads();
    if (w == 0) {
        int sv = wsum[lane];
#pragma unroll
        for (int o = 1; o < 32; o <<= 1) {
            int y = __shfl_up_sync(0xffffffffu, sv, o);
            if (lane >= o) sv += y;
        }
        wsum[lane] = sv;
    }
    __syncthreads();
    int offset = (w > 0) ? wsum[w - 1] : 0;
    if (t < NCLS) g_coff[t] = x + offset - v;
    __syncthreads();
    for (int i = t; i < BATCH; i += 1024) {
        int lab = labels[i];
        int pos = g_coff[lab] + atomicAdd(&g_cfill[lab], 1);
        g_crows[pos] = i;
    }
}

// ---------------------------------------------------------------------------
// exact hardest positive: warp per ANCHOR (critical path = cnt, not cnt^2)
// ---------------------------------------------------------------------------
__global__ void pos_kernel(const float* __restrict__ emb, const int* __restrict__ labels) {
    int wid = threadIdx.x >> 5, lane = threadIdx.x & 31;
    int row = blockIdx.x * 8 + wid;
    int lab = labels[row];
    int off = g_coff[lab], cnt = g_ccount[lab];
    float4 av = *reinterpret_cast<const float4*>(emb + (size_t)row * DIM + lane * 4);
    float sqa = g_sq[row];
    float best = -FLT_MAX; int besti = -1;
    for (int bi = 0; bi < cnt; bi++) {
        int b = g_crows[off + bi];
        if (b == row) continue;
        float4 bv = *reinterpret_cast<const float4*>(emb + (size_t)b * DIM + lane * 4);
        float d = av.x * bv.x + av.y * bv.y + av.z * bv.z + av.w * bv.w;
#pragma unroll
        for (int o = 16; o; o >>= 1) d += __shfl_xor_sync(0xffffffffu, d, o);
        float d2 = sqa + g_sq[b] - 2.f * d;
        if (d2 > best || (d2 == best && b < besti)) { best = d2; besti = b; }
    }
    if (lane == 0) g_pi[row] = besti;
}

// ---------------------------------------------------------------------------
// symmetric fp16 tensor-core Gram + bidirectional packed max-dot mining
// ---------------------------------------------------------------------------
template<bool DIAG>
__device__ __forceinline__ void mine_rows(
    const float acc[4][4][4], const uint32_t jc[8], uint32_t run[8],
    int wi, int wj, int lane)
{
#pragma unroll
    for (int mf = 0; mf < 4; mf++) {
#pragma unroll
        for (int nf = 0; nf < 4; nf++) {
#pragma unroll
            for (int e = 0; e < 4; e++) {
                int h = e >> 1, eb = e & 1;
                uint32_t bits = __float_as_uint(acc[mf][nf][e] + 2.0f);
                uint32_t pk = (bits & 0xFFFFE000u) | jc[nf * 2 + eb];
                if (DIAG) {
                    int cl = wj * 32 + nf * 8 + 2 * (lane & 3) + eb;
                    int rl = wi * 64 + mf * 16 + (lane >> 2) + 8 * h;
                    if (cl == rl) pk = 0u;
                }
                int q = mf * 2 + h;
                run[q] = run[q] > pk ? run[q] : pk;
            }
        }
    }
}

__device__ __forceinline__ void mine_cols(
    const float acc[4][4][4], int it, int jt, int wi, int wj, int lane)
{
    uint32_t colrun[8];
#pragma unroll
    for (int q = 0; q < 8; q++) colrun[q] = 0u;
    uint32_t ic[8];
#pragma unroll
    for (int mf = 0; mf < 4; mf++)
#pragma unroll
        for (int h = 0; h < 2; h++)
            ic[mf * 2 + h] =
                (uint32_t)(8191 - (it * 128 + wi * 64 + mf * 16 + (lane >> 2) + 8 * h));
#pragma unroll
    for (int mf = 0; mf < 4; mf++)
#pragma unroll
        for (int nf = 0; nf < 4; nf++)
#pragma unroll
            for (int e = 0; e < 4; e++) {
                int h = e >> 1, eb = e & 1;
                uint32_t bits = __float_as_uint(acc[mf][nf][e] + 2.0f);
                uint32_t pk = (bits & 0xFFFFE000u) | ic[mf * 2 + h];
                int q = nf * 2 + eb;
                colrun[q] = colrun[q] > pk ? colrun[q] : pk;
            }
#pragma unroll
    for (int q = 0; q < 8; q++) {
        uint32_t v = colrun[q];
        v = max(v, __shfl_xor_sync(0xffffffffu, v, 4));
        v = max(v, __shfl_xor_sync(0xffffffffu, v, 8));
        v = max(v, __shfl_xor_sync(0xffffffffu, v, 16));
        colrun[q] = v;
    }
    if ((lane >> 2) == 0) {
#pragma unroll
        for (int nf = 0; nf < 4; nf++)
#pragma unroll
            for (int eb = 0; eb < 2; eb++) {
                int col = jt * 128 + wj * 32 + nf * 8 + 2 * lane + eb;
                atomicMax(&g_packed[col], colrun[nf * 2 + eb]);
            }
    }
}

__device__ __forceinline__ void flush_rows(uint32_t run[8], int it, int wi, int lane) {
#pragma unroll
    for (int q = 0; q < 8; q++) {
        uint32_t v = run[q];
        v = max(v, __shfl_xor_sync(0xffffffffu, v, 1));
        v = max(v, __shfl_xor_sync(0xffffffffu, v, 2));
        run[q] = v;
    }
    if ((lane & 3) == 0) {
#pragma unroll
        for (int mf = 0; mf < 4; mf++)
#pragma unroll
            for (int h = 0; h < 2; h++) {
                int row = it * 128 + wi * 64 + mf * 16 + (lane >> 2) + 8 * h;
                atomicMax(&g_packed[row], run[mf * 2 + h]);
            }
    }
}

__global__ __launch_bounds__(256, 1)
void mine_kernel() {
    extern __shared__ __half smh[];
    __half* sA = smh;
    __half* sB[2] = { smh + TILEH, smh + 2 * TILEH };

    const int tid = threadIdx.x, lane = tid & 31, wid = tid >> 5;
    const int wi = wid & 1, wj = wid >> 1;
    const int k = blockIdx.x;
    const int start = 7 * k + (k < 8 ? k : 8);
    const int cnt = 7 + (k < 8 ? 1 : 0);

    auto loadA = [&](int it) {
#pragma unroll
        for (int i = 0; i < 8; i++) {
            int idx = tid + i * 256, r = idx >> 4, c = idx & 15;
            cp16(&sA[r * LDH + c * 8], g_embh + (size_t)(it * 128 + r) * DIM + c * 8);
        }
    };
    auto loadB = [&](__half* dst, int jt) {
#pragma unroll
        for (int i = 0; i < 8; i++) {
            int idx = tid + i * 256, r = idx >> 4, c = idx & 15;
            cp16(&dst[r * LDH + c * 8], g_embh + (size_t)(jt * 128 + r) * DIM + c * 8);
        }
    };

    int it0, jt0;
    dec_tile(start, it0, jt0);
    loadA(it0); loadB(sB[0], jt0);
    cpcommit();
    if (cnt > 1) { int i1, j1; dec_tile(start + 1, i1, j1); loadB(sB[1], j1); }
    cpcommit();

    int cur_it = it0;
    uint32_t run[8];
#pragma unroll
    for (int q = 0; q < 8; q++) run[q] = 0u;

    for (int s = 0; s < cnt; s++) {
        int it, jt;
        dec_tile(start + s, it, jt);
        if (it != cur_it) {
            flush_rows(run, cur_it, wi, lane);
#pragma unroll
            for (int q = 0; q < 8; q++) run[q] = 0u;
            cpwait<0>(); __syncthreads();
            loadA(it); cpcommit();
            cpwait<0>(); __syncthreads();
            cur_it = it;
        } else {
            cpwait<1>(); __syncthreads();
        }
        const __half* bB = sB[s & 1];

        float acc[4][4][4];
#pragma unroll
        for (int mf = 0; mf < 4; mf++)
#pragma unroll
            for (int nf = 0; nf < 4; nf++)
#pragma unroll
                for (int e = 0; e < 4; e++) acc[mf][nf][e] = 0.f;

#pragma unroll
        for (int ks = 0; ks < 8; ks++) {
            const int k0 = ks * 16;
            uint32_t a[4][4], b[4][2];
#pragma unroll
            for (int mf = 0; mf < 4; mf++) {
                int r0 = wi * 64 + mf * 16 + (lane >> 2);
                const __half* pa = sA + r0 * LDH + k0 + 2 * (lane & 3);
                a[mf][0] = *(const uint32_t*)(pa);
                a[mf][1] = *(const uint32_t*)(pa + 8 * LDH);
                a[mf][2] = *(const uint32_t*)(pa + 8);
                a[mf][3] = *(const uint32_t*)(pa + 8 * LDH + 8);
            }
#pragma unroll
            for (int nf = 0; nf < 4; nf++) {
                int n0 = wj * 32 + nf * 8 + (lane >> 2);
                const __half* pb = bB + n0 * LDH + k0 + 2 * (lane & 3);
                b[nf][0] = *(const uint32_t*)(pb);
                b[nf][1] = *(const uint32_t*)(pb + 8);
            }
#pragma unroll
            for (int mf = 0; mf < 4; mf++)
#pragma unroll
                for (int nf = 0; nf < 4; nf++)
                    mma16(acc[mf][nf], a[mf], b[nf]);
        }
        __syncthreads();

        if (s + 2 < cnt) {
            int i2, j2;
            dec_tile(start + s + 2, i2, j2);
            loadB(sB[s & 1], j2);
            cpcommit();
        }

        uint32_t jc[8];
#pragma unroll
        for (int nf = 0; nf < 4; nf++)
#pragma unroll
            for (int eb = 0; eb < 2; eb++)
                jc[nf * 2 + eb] =
                    (uint32_t)(8191 - (jt * 128 + wj * 32 + nf * 8 + 2 * (lane & 3) + eb));

        if (it == jt) {
            mine_rows<true>(acc, jc, run, wi, wj, lane);
        } else {
            mine_rows<false>(acc, jc, run, wi, wj, lane);
            mine_cols(acc, it, jt, wi, wj, lane);
        }
    }
    flush_rows(run, cur_it, wi, lane);
}

// ---------------------------------------------------------------------------
__global__ void flag_kernel(const int* __restrict__ labels) {
    int row = blockIdx.x * 256 + threadIdx.x;
    uint32_t pk = g_packed[row];
    int ni = 8191 - (int)(pk & 0x1FFFu);
    if (labels[ni] == labels[row]) {
        int s = atomicAdd(&g_nflag, 1);
        if (s < 512) g_flagrows[s] = row;
    } else {
        g_ni[row] = ni;
    }
}

__global__ void patch_kernel(const float* __restrict__ emb, const int* __restrict__ labels) {
    __shared__ float erow[DIM];
    __shared__ float sval[256];
    __shared__ int   sidx[256];
    int tid = threadIdx.x;
    for (int f = blockIdx.x; f < g_nflag; f += gridDim.x) {
        __syncthreads();
        int row = g_flagrows[f];
        int li = labels[row];
        if (tid < DIM) erow[tid] = emb[(size_t)row * DIM + tid];
        __syncthreads();
        float sqr = g_sq[row];
        float bv = FLT_MAX; int bi = BATCH;
        for (int j = tid; j < BATCH; j += 256) {
            if (labels[j] == li) continue;
            float d = 0.f;
            const float4* ej = reinterpret_cast<const float4*>(emb + (size_t)j * DIM);
#pragma unroll
            for (int kk = 0; kk < 32; kk++) {
                float4 v = ej[kk];
                const float4 a = *reinterpret_cast<const float4*>(&erow[kk * 4]);
                d += a.x * v.x + a.y * v.y + a.z * v.z + a.w * v.w;
            }
            float d2 = sqr + g_sq[j] - 2.f * d;
            if (d2 < bv || (d2 == bv && j < bi)) { bv = d2; bi = j; }
        }
        sval[tid] = bv; sidx[tid] = bi;
        __syncthreads();
        for (int o = 128; o; o >>= 1) {
            if (tid < o) {
                float ov = sval[tid + o]; int oi = sidx[tid + o];
                if (ov < sval[tid] || (ov == sval[tid] && oi < sidx[tid])) {
                    sval[tid] = ov; sidx[tid] = oi;
                }
            }
            __syncthreads();
        }
        if (tid == 0) g_ni[row] = sidx[0];
    }
}

// ---------------------------------------------------------------------------
__global__ void finalize_kernel(const float* __restrict__ emb) {
    __shared__ float s_tri[8];
    __shared__ int   s_cnt[8];
    int wid = threadIdx.x >> 5, lane = threadIdx.x & 31;
    int row = blockIdx.x * 8 + wid;
    int pi = g_pi[row];
    int ni = g_ni[row];
    bool valid = (pi >= 0);
    float per = 0.f;
    if (valid) {
        const float eps = 1e-6f;
        float4 a = *reinterpret_cast<const float4*>(emb + (size_t)row * DIM + lane * 4);
        float4 p = *reinterpret_cast<const float4*>(emb + (size_t)pi * DIM + lane * 4);
        float4 n = *reinterpret_cast<const float4*>(emb + (size_t)ni * DIM + lane * 4);
        float dx = a.x - p.x + eps, dy = a.y - p.y + eps, dz = a.z - p.z + eps, dw = a.w - p.w + eps;
        float sp = dx * dx + dy * dy + dz * dz + dw * dw;
        dx = a.x - n.x + eps; dy = a.y - n.y + eps; dz = a.z - n.z + eps; dw = a.w - n.w + eps;
        float sn = dx * dx + dy * dy + dz * dz + dw * dw;
#pragma unroll
        for (int off = 16; off; off >>= 1) {
            sp += __shfl_xor_sync(0xffffffffu, sp, off);
            sn += __shfl_xor_sync(0xffffffffu, sn, off);
        }
        per = fmaxf(sqrtf(sp) - sqrtf(sn) + 0.5f, 0.f);
    }
    if (lane == 0) { s_tri[wid] = valid ? per : 0.f; s_cnt[wid] = valid ? 1 : 0; }
    __syncthreads();
    if (threadIdx.x == 0) {
        float b = 0.f; int c = 0;
#pragma unroll
        for (int w = 0; w < 8; w++) { b += s_tri[w]; c += s_cnt[w]; }
        atomicAdd(&g_tri, b);
        atomicAdd(&g_cnt, c);
    }
}

__global__ void combine_kernel(float* out) {
    float ce = g_ce * (1.0f / (float)BATCH);
    float tri = (g_cnt > 0) ? (g_tri / (float)g_cnt) : 0.f;
    out[0] = ce + tri;
}

// ---------------------------------------------------------------------------
extern "C" void kernel_launch(void* const* d_in, const int* in_sizes, int n_in,
                              void* d_out, int out_size) {
    const float* logits = (const float*)d_in[0];
    const float* emb    = (const float*)d_in[1];
    const int*   labels = (const int*)d_in[2];
    float* out = (float*)d_out;

    cudaFuncSetAttribute(mine_kernel, cudaFuncAttributeMaxDynamicSharedMemorySize, SMEM_BYTES);

    init_kernel<<<32, 256>>>();
    prep_kernel<<<BATCH / 8, 256>>>(emb, labels);
    ce_kernel<<<BATCH / 8, 256>>>(logits, labels);
    scan_scatter_kernel<<<1, 1024>>>(labels);
    pos_kernel<<<BATCH / 8, 256>>>(emb, labels);
    mine_kernel<<<NCTA, 256, SMEM_BYTES>>>();
    flag_kernel<<<32, 256>>>(labels);
    patch_kernel<<<128, 256>>>(emb, labels);
    finalize_kernel<<<BATCH / 8, 256>>>(emb);
    combine_kernel<<<1, 1>>>(out);
}

// round 7
// speedup vs baseline: 2.3076x; 1.0802x over previous
#include <cuda_runtime.h>
#include <cuda_fp16.h>
#include <math.h>
#include <float.h>
#include <stdint.h>

#define BATCH 8192
#define DIM   128
#define NCLS  1000
#define LDH 136                       /* padded halves per row (272B) */
#define TILEH (128 * LDH)             /* halves per tile (34816 B)    */
#define SMEM_BYTES (3 * TILEH * 2)
#define NCTA 296

// ---- device scratch ----
__device__ __half   g_embh[BATCH * DIM];
__device__ float    g_sq[BATCH];
__device__ uint32_t g_packed[BATCH];   // (dot+2 bits & ~0x1FFF) | (8191-idx)
__device__ int      g_pi[BATCH];
__device__ int      g_ni[BATCH];
__device__ int      g_ccount[NCLS];
__device__ int      g_coff[NCLS];
__device__ int      g_crows[BATCH];
__device__ int      g_flagrows[512];
__device__ int      g_nflag;
__device__ float    g_ce;
__device__ float    g_tri;
__device__ int      g_cnt;

// ================= helpers =================
__device__ __forceinline__ uint32_t smem_u32(const void* p) {
    uint32_t a;
    asm("{ .reg .u64 t; cvta.to.shared.u64 t, %1; cvt.u32.u64 %0, t; }" : "=r"(a) : "l"(p));
    return a;
}
__device__ __forceinline__ void cp16(void* s, const void* g) {
    uint32_t sa = smem_u32(s);
    asm volatile("cp.async.cg.shared.global [%0], [%1], 16;" :: "r"(sa), "l"(g));
}
__device__ __forceinline__ void cpcommit() { asm volatile("cp.async.commit_group;"); }
template<int N> __device__ __forceinline__ void cpwait() {
    asm volatile("cp.async.wait_group %0;" :: "n"(N));
}
__device__ __forceinline__ void mma16(float* c, const uint32_t* a, const uint32_t* b) {
    asm volatile(
        "mma.sync.aligned.m16n8k16.row.col.f32.f16.f16.f32 "
        "{%0,%1,%2,%3}, {%4,%5,%6,%7}, {%8,%9}, {%0,%1,%2,%3};"
        : "+f"(c[0]), "+f"(c[1]), "+f"(c[2]), "+f"(c[3])
        : "r"(a[0]), "r"(a[1]), "r"(a[2]), "r"(a[3]), "r"(b[0]), "r"(b[1]));
}

// triangular decode: linear tile id -> (it, jt), jt >= it, strips of length 64-it
__device__ __forceinline__ void dec_tile(int L, int& it, int& jt) {
    int c = 0, r = 0;
#pragma unroll 1
    while (c + (64 - r) <= L) { c += 64 - r; r++; }
    it = r; jt = r + (L - c);
}

// ---------------------------------------------------------------------------
__global__ void init_kernel() {
    int i = blockIdx.x * 256 + threadIdx.x;
    if (i < BATCH) g_packed[i] = 0u;
    if (i == 0) { g_ce = 0.f; g_tri = 0.f; g_cnt = 0; g_nflag = 0; }
}

// prep: sq norms + f32->f16 conversion (warp per row)
__global__ void prep_kernel(const float* __restrict__ emb) {
    int wid = threadIdx.x >> 5, lane = threadIdx.x & 31;
    int row = blockIdx.x * 8 + wid;
    float4 v = *reinterpret_cast<const float4*>(emb + (size_t)row * DIM + lane * 4);
    __half2 h01 = __floats2half2_rn(v.x, v.y);
    __half2 h23 = __floats2half2_rn(v.z, v.w);
    uint2 hw = make_uint2(*(uint32_t*)&h01, *(uint32_t*)&h23);
    *reinterpret_cast<uint2*>(&g_embh[(size_t)row * DIM + lane * 4]) = hw;
    float s = v.x * v.x + v.y * v.y + v.z * v.z + v.w * v.w;
#pragma unroll
    for (int off = 16; off; off >>= 1) s += __shfl_xor_sync(0xffffffffu, s, off);
    if (lane == 0) g_sq[row] = s;
}

// ---------------------------------------------------------------------------
// cross entropy, float4 loads (1000 = 250 vec4)
// ---------------------------------------------------------------------------
__global__ void ce_kernel(const float* __restrict__ logits, const int* __restrict__ labels) {
    __shared__ float warp_loss[8];
    int wid = threadIdx.x >> 5, lane = threadIdx.x & 31;
    int row = blockIdx.x * 8 + wid;
    const float* x = logits + (size_t)row * NCLS;
    float m = -FLT_MAX, s = 0.f, sx = 0.f;
#pragma unroll
    for (int i = 0; i < 8; i++) {
        int c4 = lane + 32 * i;
        if (c4 < 250) {
            float4 v = __ldg(reinterpret_cast<const float4*>(x) + c4);
            sx += v.x + v.y + v.z + v.w;
            float ml = fmaxf(fmaxf(v.x, v.y), fmaxf(v.z, v.w));
            float sl = __expf(v.x - ml) + __expf(v.y - ml) +
                       __expf(v.z - ml) + __expf(v.w - ml);
            float nm = fmaxf(m, ml);
            s = s * __expf(m - nm) + sl * __expf(ml - nm);
            m = nm;
        }
    }
#pragma unroll
    for (int off = 16; off; off >>= 1) {
        float om = __shfl_xor_sync(0xffffffffu, m, off);
        float os = __shfl_xor_sync(0xffffffffu, s, off);
        float nm = fmaxf(m, om);
        s = s * __expf(m - nm) + os * __expf(om - nm);
        m = nm;
        sx += __shfl_xor_sync(0xffffffffu, sx, off);
    }
    if (lane == 0) {
        float lse = m + logf(s);
        float xl  = __ldg(x + labels[row]);
        warp_loss[wid] = 0.9f * (lse - xl) + 0.1f * (lse - sx * (1.0f / (float)NCLS));
    }
    __syncthreads();
    if (threadIdx.x == 0) {
        float b = 0.f;
#pragma unroll
        for (int w = 0; w < 8; w++) b += warp_loss[w];
        atomicAdd(&g_ce, b);
    }
}

// ---------------------------------------------------------------------------
// fused smem histogram + shuffle scan + smem-counter scatter (single block)
// ---------------------------------------------------------------------------
__global__ void class_kernel(const int* __restrict__ labels) {
    __shared__ int hist[NCLS];
    __shared__ int fill[NCLS];
    __shared__ int wsum[32];
    int t = threadIdx.x, lane = t & 31, w = t >> 5;
    if (t < NCLS) { hist[t] = 0; fill[t] = 0; }
    __syncthreads();
#pragma unroll
    for (int i = 0; i < 8; i++) atomicAdd(&hist[labels[t + 1024 * i]], 1);
    __syncthreads();
    int v = (t < NCLS) ? hist[t] : 0;
    int x = v;
#pragma unroll
    for (int o = 1; o < 32; o <<= 1) {
        int y = __shfl_up_sync(0xffffffffu, x, o);
        if (lane >= o) x += y;
    }
    if (lane == 31) wsum[w] = x;
    __syncthreads();
    if (w == 0) {
        int sv = wsum[lane];
#pragma unroll
        for (int o = 1; o < 32; o <<= 1) {
            int y = __shfl_up_sync(0xffffffffu, sv, o);
            if (lane >= o) sv += y;
        }
        wsum[lane] = sv;
    }
    __syncthreads();
    int offset = (w > 0) ? wsum[w - 1] : 0;
    int myoff = x + offset - v;
    if (t < NCLS) { g_coff[t] = myoff; g_ccount[t] = v; hist[t] = myoff; }
    __syncthreads();
#pragma unroll
    for (int i = 0; i < 8; i++) {
        int idx = t + 1024 * i;
        int lab = labels[idx];
        int pos = hist[lab] + atomicAdd(&fill[lab], 1);
        g_crows[pos] = idx;
    }
}

// ---------------------------------------------------------------------------
// exact hardest positive: warp per ANCHOR
// ---------------------------------------------------------------------------
__global__ void pos_kernel(const float* __restrict__ emb, const int* __restrict__ labels) {
    int wid = threadIdx.x >> 5, lane = threadIdx.x & 31;
    int row = blockIdx.x * 8 + wid;
    int lab = labels[row];
    int off = g_coff[lab], cnt = g_ccount[lab];
    float4 av = *reinterpret_cast<const float4*>(emb + (size_t)row * DIM + lane * 4);
    float sqa = g_sq[row];
    float best = -FLT_MAX; int besti = -1;
    for (int bi = 0; bi < cnt; bi++) {
        int b = g_crows[off + bi];
        if (b == row) continue;
        float4 bv = *reinterpret_cast<const float4*>(emb + (size_t)b * DIM + lane * 4);
        float d = av.x * bv.x + av.y * bv.y + av.z * bv.z + av.w * bv.w;
#pragma unroll
        for (int o = 16; o; o >>= 1) d += __shfl_xor_sync(0xffffffffu, d, o);
        float d2 = sqa + g_sq[b] - 2.f * d;
        if (d2 > best || (d2 == best && b < besti)) { best = d2; besti = b; }
    }
    if (lane == 0) g_pi[row] = besti;
}

// ---------------------------------------------------------------------------
// symmetric fp16 tensor-core Gram + bidirectional packed max-dot mining
// ---------------------------------------------------------------------------
template<bool DIAG>
__device__ __forceinline__ void mine_rows(
    const float acc[4][4][4], const uint32_t jc[8], uint32_t run[8],
    int wi, int wj, int lane)
{
#pragma unroll
    for (int mf = 0; mf < 4; mf++) {
#pragma unroll
        for (int nf = 0; nf < 4; nf++) {
#pragma unroll
            for (int e = 0; e < 4; e++) {
                int h = e >> 1, eb = e & 1;
                uint32_t bits = __float_as_uint(acc[mf][nf][e] + 2.0f);
                uint32_t pk = (bits & 0xFFFFE000u) | jc[nf * 2 + eb];
                if (DIAG) {
                    int cl = wj * 32 + nf * 8 + 2 * (lane & 3) + eb;
                    int rl = wi * 64 + mf * 16 + (lane >> 2) + 8 * h;
                    if (cl == rl) pk = 0u;
                }
                int q = mf * 2 + h;
                run[q] = run[q] > pk ? run[q] : pk;
            }
        }
    }
}

__device__ __forceinline__ void mine_cols(
    const float acc[4][4][4], int it, int jt, int wi, int wj, int lane)
{
    uint32_t colrun[8];
#pragma unroll
    for (int q = 0; q < 8; q++) colrun[q] = 0u;
    uint32_t ic[8];
#pragma unroll
    for (int mf = 0; mf < 4; mf++)
#pragma unroll
        for (int h = 0; h < 2; h++)
            ic[mf * 2 + h] =
                (uint32_t)(8191 - (it * 128 + wi * 64 + mf * 16 + (lane >> 2) + 8 * h));
#pragma unroll
    for (int mf = 0; mf < 4; mf++)
#pragma unroll
        for (int nf = 0; nf < 4; nf++)
#pragma unroll
            for (int e = 0; e < 4; e++) {
                int h = e >> 1, eb = e & 1;
                uint32_t bits = __float_as_uint(acc[mf][nf][e] + 2.0f);
                uint32_t pk = (bits & 0xFFFFE000u) | ic[mf * 2 + h];
                int q = nf * 2 + eb;
                colrun[q] = colrun[q] > pk ? colrun[q] : pk;
            }
#pragma unroll
    for (int q = 0; q < 8; q++) {
        uint32_t v = colrun[q];
        v = max(v, __shfl_xor_sync(0xffffffffu, v, 4));
        v = max(v, __shfl_xor_sync(0xffffffffu, v, 8));
        v = max(v, __shfl_xor_sync(0xffffffffu, v, 16));
        colrun[q] = v;
    }
    if ((lane >> 2) == 0) {
#pragma unroll
        for (int nf = 0; nf < 4; nf++)
#pragma unroll
            for (int eb = 0; eb < 2; eb++) {
                int col = jt * 128 + wj * 32 + nf * 8 + 2 * lane + eb;
                atomicMax(&g_packed[col], colrun[nf * 2 + eb]);
            }
    }
}

__device__ __forceinline__ void flush_rows(uint32_t run[8], int it, int wi, int lane) {
#pragma unroll
    for (int q = 0; q < 8; q++) {
        uint32_t v = run[q];
        v = max(v, __shfl_xor_sync(0xffffffffu, v, 1));
        v = max(v, __shfl_xor_sync(0xffffffffu, v, 2));
        run[q] = v;
    }
    if ((lane & 3) == 0) {
#pragma unroll
        for (int mf = 0; mf < 4; mf++)
#pragma unroll
            for (int h = 0; h < 2; h++) {
                int row = it * 128 + wi * 64 + mf * 16 + (lane >> 2) + 8 * h;
                atomicMax(&g_packed[row], run[mf * 2 + h]);
            }
    }
}

__global__ __launch_bounds__(256, 2)
void mine_kernel() {
    extern __shared__ __half smh[];
    __half* sA = smh;
    __half* sB[2] = { smh + TILEH, smh + 2 * TILEH };

    const int tid = threadIdx.x, lane = tid & 31, wid = tid >> 5;
    const int wi = wid & 1, wj = wid >> 1;
    const int k = blockIdx.x;
    const int start = 7 * k + (k < 8 ? k : 8);
    const int cnt = 7 + (k < 8 ? 1 : 0);

    auto loadA = [&](int it) {
#pragma unroll
        for (int i = 0; i < 8; i++) {
            int idx = tid + i * 256, r = idx >> 4, c = idx & 15;
            cp16(&sA[r * LDH + c * 8], g_embh + (size_t)(it * 128 + r) * DIM + c * 8);
        }
    };
    auto loadB = [&](__half* dst, int jt) {
#pragma unroll
        for (int i = 0; i < 8; i++) {
            int idx = tid + i * 256, r = idx >> 4, c = idx & 15;
            cp16(&dst[r * LDH + c * 8], g_embh + (size_t)(jt * 128 + r) * DIM + c * 8);
        }
    };

    int it0, jt0;
    dec_tile(start, it0, jt0);
    loadA(it0); loadB(sB[0], jt0);
    cpcommit();
    if (cnt > 1) { int i1, j1; dec_tile(start + 1, i1, j1); loadB(sB[1], j1); }
    cpcommit();

    int cur_it = it0;
    uint32_t run[8];
#pragma unroll
    for (int q = 0; q < 8; q++) run[q] = 0u;

    for (int s = 0; s < cnt; s++) {
        int it, jt;
        dec_tile(start + s, it, jt);
        if (it != cur_it) {
            flush_rows(run, cur_it, wi, lane);
#pragma unroll
            for (int q = 0; q < 8; q++) run[q] = 0u;
            cpwait<0>(); __syncthreads();
            loadA(it); cpcommit();
            cpwait<0>(); __syncthreads();
            cur_it = it;
        } else {
            cpwait<1>(); __syncthreads();
        }
        const __half* bB = sB[s & 1];

        float acc[4][4][4];
#pragma unroll
        for (int mf = 0; mf < 4; mf++)
#pragma unroll
            for (int nf = 0; nf < 4; nf++)
#pragma unroll
                for (int e = 0; e < 4; e++) acc[mf][nf][e] = 0.f;

#pragma unroll
        for (int ks = 0; ks < 8; ks++) {
            const int k0 = ks * 16;
            uint32_t a[4][4], b[4][2];
#pragma unroll
            for (int mf = 0; mf < 4; mf++) {
                int r0 = wi * 64 + mf * 16 + (lane >> 2);
                const __half* pa = sA + r0 * LDH + k0 + 2 * (lane & 3);
                a[mf][0] = *(const uint32_t*)(pa);
                a[mf][1] = *(const uint32_t*)(pa + 8 * LDH);
                a[mf][2] = *(const uint32_t*)(pa + 8);
                a[mf][3] = *(const uint32_t*)(pa + 8 * LDH + 8);
            }
#pragma unroll
            for (int nf = 0; nf < 4; nf++) {
                int n0 = wj * 32 + nf * 8 + (lane >> 2);
                const __half* pb = bB + n0 * LDH + k0 + 2 * (lane & 3);
                b[nf][0] = *(const uint32_t*)(pb);
                b[nf][1] = *(const uint32_t*)(pb + 8);
            }
#pragma unroll
            for (int mf = 0; mf < 4; mf++)
#pragma unroll
                for (int nf = 0; nf < 4; nf++)
                    mma16(acc[mf][nf], a[mf], b[nf]);
        }
        __syncthreads();

        if (s + 2 < cnt) {
            int i2, j2;
            dec_tile(start + s + 2, i2, j2);
            loadB(sB[s & 1], j2);
            cpcommit();
        }

        uint32_t jc[8];
#pragma unroll
        for (int nf = 0; nf < 4; nf++)
#pragma unroll
            for (int eb = 0; eb < 2; eb++)
                jc[nf * 2 + eb] =
                    (uint32_t)(8191 - (jt * 128 + wj * 32 + nf * 8 + 2 * (lane & 3) + eb));

        if (it == jt) {
            mine_rows<true>(acc, jc, run, wi, wj, lane);
        } else {
            mine_rows<false>(acc, jc, run, wi, wj, lane);
            mine_cols(acc, it, jt, wi, wj, lane);
        }
    }
    flush_rows(run, cur_it, wi, lane);
}

// ---------------------------------------------------------------------------
__global__ void flag_kernel(const int* __restrict__ labels) {
    int row = blockIdx.x * 256 + threadIdx.x;
    uint32_t pk = g_packed[row];
    int ni = 8191 - (int)(pk & 0x1FFFu);
    if (labels[ni] == labels[row]) {
        int s = atomicAdd(&g_nflag, 1);
        if (s < 512) g_flagrows[s] = row;
    } else {
        g_ni[row] = ni;
    }
}

__global__ void patch_kernel(const float* __restrict__ emb, const int* __restrict__ labels) {
    __shared__ float erow[DIM];
    __shared__ float sval[256];
    __shared__ int   sidx[256];
    int tid = threadIdx.x;
    for (int f = blockIdx.x; f < g_nflag; f += gridDim.x) {
        __syncthreads();
        int row = g_flagrows[f];
        int li = labels[row];
        if (tid < DIM) erow[tid] = emb[(size_t)row * DIM + tid];
        __syncthreads();
        float sqr = g_sq[row];
        float bv = FLT_MAX; int bi = BATCH;
        for (int j = tid; j < BATCH; j += 256) {
            if (labels[j] == li) continue;
            float d = 0.f;
            const float4* ej = reinterpret_cast<const float4*>(emb + (size_t)j * DIM);
#pragma unroll
            for (int kk = 0; kk < 32; kk++) {
                float4 v = ej[kk];
                const float4 a = *reinterpret_cast<const float4*>(&erow[kk * 4]);
                d += a.x * v.x + a.y * v.y + a.z * v.z + a.w * v.w;
            }
            float d2 = sqr + g_sq[j] - 2.f * d;
            if (d2 < bv || (d2 == bv && j < bi)) { bv = d2; bi = j; }
        }
        sval[tid] = bv; sidx[tid] = bi;
        __syncthreads();
        for (int o = 128; o; o >>= 1) {
            if (tid < o) {
                float ov = sval[tid + o]; int oi = sidx[tid + o];
                if (ov < sval[tid] || (ov == sval[tid] && oi < sidx[tid])) {
                    sval[tid] = ov; sidx[tid] = oi;
                }
            }
            __syncthreads();
        }
        if (tid == 0) g_ni[row] = sidx[0];
    }
}

// ---------------------------------------------------------------------------
__global__ void finalize_kernel(const float* __restrict__ emb) {
    __shared__ float s_tri[8];
    __shared__ int   s_cnt[8];
    int wid = threadIdx.x >> 5, lane = threadIdx.x & 31;
    int row = blockIdx.x * 8 + wid;
    int pi = g_pi[row];
    int ni = g_ni[row];
    bool valid = (pi >= 0);
    float per = 0.f;
    if (valid) {
        const float eps = 1e-6f;
        float4 a = *reinterpret_cast<const float4*>(emb + (size_t)row * DIM + lane * 4);
        float4 p = *reinterpret_cast<const float4*>(emb + (size_t)pi * DIM + lane * 4);
        float4 n = *reinterpret_cast<const float4*>(emb + (size_t)ni * DIM + lane * 4);
        float dx = a.x - p.x + eps, dy = a.y - p.y + eps, dz = a.z - p.z + eps, dw = a.w - p.w + eps;
        float sp = dx * dx + dy * dy + dz * dz + dw * dw;
        dx = a.x - n.x + eps; dy = a.y - n.y + eps; dz = a.z - n.z + eps; dw = a.w - n.w + eps;
        float sn = dx * dx + dy * dy + dz * dz + dw * dw;
#pragma unroll
        for (int off = 16; off; off >>= 1) {
            sp += __shfl_xor_sync(0xffffffffu, sp, off);
            sn += __shfl_xor_sync(0xffffffffu, sn, off);
        }
        per = fmaxf(sqrtf(sp) - sqrtf(sn) + 0.5f, 0.f);
    }
    if (lane == 0) { s_tri[wid] = valid ? per : 0.f; s_cnt[wid] = valid ? 1 : 0; }
    __syncthreads();
    if (threadIdx.x == 0) {
        float b = 0.f; int c = 0;
#pragma unroll
        for (int w = 0; w < 8; w++) { b += s_tri[w]; c += s_cnt[w]; }
        atomicAdd(&g_tri, b);
        atomicAdd(&g_cnt, c);
    }
}

__global__ void combine_kernel(float* out) {
    float ce = g_ce * (1.0f / (float)BATCH);
    float tri = (g_cnt > 0) ? (g_tri / (float)g_cnt) : 0.f;
    out[0] = ce + tri;
}

// ---------------------------------------------------------------------------
extern "C" void kernel_launch(void* const* d_in, const int* in_sizes, int n_in,
                              void* d_out, int out_size) {
    const float* logits = (const float*)d_in[0];
    const float* emb    = (const float*)d_in[1];
    const int*   labels = (const int*)d_in[2];
    float* out = (float*)d_out;

    cudaFuncSetAttribute(mine_kernel, cudaFuncAttributeMaxDynamicSharedMemorySize, SMEM_BYTES);

    init_kernel<<<32, 256>>>();
    prep_kernel<<<BATCH / 8, 256>>>(emb);
    ce_kernel<<<BATCH / 8, 256>>>(logits, labels);
    mine_kernel<<<NCTA, 256, SMEM_BYTES>>>();          // 4th launch -> ncu profiles this
    class_kernel<<<1, 1024>>>(labels);
    pos_kernel<<<BATCH / 8, 256>>>(emb, labels);
    flag_kernel<<<32, 256>>>(labels);
    patch_kernel<<<128, 256>>>(emb, labels);
    finalize_kernel<<<BATCH / 8, 256>>>(emb);
    combine_kernel<<<1, 1>>>(out);
}

// round 9
// speedup vs baseline: 5.1596x; 2.2359x over previous
#include <cuda_runtime.h>
#include <cuda_fp16.h>
#include <math.h>
#include <float.h>
#include <stdint.h>

#define BATCH 8192
#define DIM   128
#define NCLS  1000
#define LDH 136                       /* padded halves per row (272B) */
#define TILEH (128 * LDH)             /* halves per tile (34816 B)    */
#define SMEM_BYTES (3 * TILEH * 2)
#define NCTA 296
#define MAXFLAG 128

// ---- device scratch ----
__device__ __half   g_embh[BATCH * DIM];
__device__ float    g_sq[BATCH];
__device__ uint32_t g_packed[BATCH];   // (dot+2 bits & ~0x1FFF) | (8191-idx)
__device__ uint32_t g_patch[BATCH];    // (d2 bits & ~0x1FFF) | idx  (min)
__device__ int      g_pi[BATCH];
__device__ int      g_ni[BATCH];
__device__ int      g_ccount[NCLS];
__device__ int      g_coff[NCLS];
__device__ int      g_crows[BATCH];
__device__ int      g_flagrows[MAXFLAG];
__device__ int      g_nflag;
__device__ float    g_ce_part[BATCH / 8];
__device__ float    g_tri_part[BATCH / 8];
__device__ int      g_cnt_part[BATCH / 8];

// ================= helpers =================
__device__ __forceinline__ uint32_t smem_u32(const void* p) {
    uint32_t a;
    asm("{ .reg .u64 t; cvta.to.shared.u64 t, %1; cvt.u32.u64 %0, t; }" : "=r"(a) : "l"(p));
    return a;
}
__device__ __forceinline__ void cp16(void* s, const void* g) {
    uint32_t sa = smem_u32(s);
    asm volatile("cp.async.cg.shared.global [%0], [%1], 16;" :: "r"(sa), "l"(g));
}
__device__ __forceinline__ void cpcommit() { asm volatile("cp.async.commit_group;"); }
template<int N> __device__ __forceinline__ void cpwait() {
    asm volatile("cp.async.wait_group %0;" :: "n"(N));
}
__device__ __forceinline__ void mma16(float* c, const uint32_t* a, const uint32_t* b) {
    asm volatile(
        "mma.sync.aligned.m16n8k16.row.col.f32.f16.f16.f32 "
        "{%0,%1,%2,%3}, {%4,%5,%6,%7}, {%8,%9}, {%0,%1,%2,%3};"
        : "+f"(c[0]), "+f"(c[1]), "+f"(c[2]), "+f"(c[3])
        : "r"(a[0]), "r"(a[1]), "r"(a[2]), "r"(a[3]), "r"(b[0]), "r"(b[1]));
}
__device__ __forceinline__ void dec_tile(int L, int& it, int& jt) {
    int c = 0, r = 0;
#pragma unroll 1
    while (c + (64 - r) <= L) { c += 64 - r; r++; }
    it = r; jt = r + (L - c);
}

// ---------------------------------------------------------------------------
// prep: sq norms + f32->f16 conversion + zero g_packed/g_nflag (warp per row)
// ---------------------------------------------------------------------------
__global__ void prep_kernel(const float* __restrict__ emb) {
    int wid = threadIdx.x >> 5, lane = threadIdx.x & 31;
    int row = blockIdx.x * 8 + wid;
    int gt = blockIdx.x * 256 + threadIdx.x;
    if (gt < BATCH) g_packed[gt] = 0u;
    if (gt == 0) g_nflag = 0;
    float4 v = *reinterpret_cast<const float4*>(emb + (size_t)row * DIM + lane * 4);
    __half2 h01 = __floats2half2_rn(v.x, v.y);
    __half2 h23 = __floats2half2_rn(v.z, v.w);
    uint2 hw = make_uint2(*(uint32_t*)&h01, *(uint32_t*)&h23);
    *reinterpret_cast<uint2*>(&g_embh[(size_t)row * DIM + lane * 4]) = hw;
    float s = v.x * v.x + v.y * v.y + v.z * v.z + v.w * v.w;
#pragma unroll
    for (int off = 16; off; off >>= 1) s += __shfl_xor_sync(0xffffffffu, s, off);
    if (lane == 0) g_sq[row] = s;
}

// ---------------------------------------------------------------------------
// cross entropy, float4 loads, per-block partial (no atomics)
// ---------------------------------------------------------------------------
__global__ void ce_kernel(const float* __restrict__ logits, const int* __restrict__ labels) {
    __shared__ float warp_loss[8];
    int wid = threadIdx.x >> 5, lane = threadIdx.x & 31;
    int row = blockIdx.x * 8 + wid;
    const float* x = logits + (size_t)row * NCLS;
    float m = -FLT_MAX, s = 0.f, sx = 0.f;
#pragma unroll
    for (int i = 0; i < 8; i++) {
        int c4 = lane + 32 * i;
        if (c4 < 250) {
            float4 v = __ldg(reinterpret_cast<const float4*>(x) + c4);
            sx += v.x + v.y + v.z + v.w;
            float ml = fmaxf(fmaxf(v.x, v.y), fmaxf(v.z, v.w));
            float sl = __expf(v.x - ml) + __expf(v.y - ml) +
                       __expf(v.z - ml) + __expf(v.w - ml);
            float nm = fmaxf(m, ml);
            s = s * __expf(m - nm) + sl * __expf(ml - nm);
            m = nm;
        }
    }
#pragma unroll
    for (int off = 16; off; off >>= 1) {
        float om = __shfl_xor_sync(0xffffffffu, m, off);
        float os = __shfl_xor_sync(0xffffffffu, s, off);
        float nm = fmaxf(m, om);
        s = s * __expf(m - nm) + os * __expf(om - nm);
        m = nm;
        sx += __shfl_xor_sync(0xffffffffu, sx, off);
    }
    if (lane == 0) {
        float lse = m + logf(s);
        float xl  = __ldg(x + labels[row]);
        warp_loss[wid] = 0.9f * (lse - xl) + 0.1f * (lse - sx * (1.0f / (float)NCLS));
    }
    __syncthreads();
    if (threadIdx.x == 0) {
        float b = 0.f;
#pragma unroll
        for (int w = 0; w < 8; w++) b += warp_loss[w];
        g_ce_part[blockIdx.x] = b;
    }
}

// ---------------------------------------------------------------------------
// fused smem histogram + shuffle scan + smem-counter scatter (single block)
// ---------------------------------------------------------------------------
__global__ void class_kernel(const int* __restrict__ labels) {
    __shared__ int hist[NCLS];
    __shared__ int fill[NCLS];
    __shared__ int wsum[32];
    int t = threadIdx.x, lane = t & 31, w = t >> 5;
    if (t < NCLS) { hist[t] = 0; fill[t] = 0; }
    __syncthreads();
#pragma unroll
    for (int i = 0; i < 8; i++) atomicAdd(&hist[labels[t + 1024 * i]], 1);
    __syncthreads();
    int v = (t < NCLS) ? hist[t] : 0;
    int x = v;
#pragma unroll
    for (int o = 1; o < 32; o <<= 1) {
        int y = __shfl_up_sync(0xffffffffu, x, o);
        if (lane >= o) x += y;
    }
    if (lane == 31) wsum[w] = x;
    __syncthreads();
    if (w == 0) {
        int sv = wsum[lane];
#pragma unroll
        for (int o = 1; o < 32; o <<= 1) {
            int y = __shfl_up_sync(0xffffffffu, sv, o);
            if (lane >= o) sv += y;
        }
        wsum[lane] = sv;
    }
    __syncthreads();
    int offset = (w > 0) ? wsum[w - 1] : 0;
    int myoff = x + offset - v;
    if (t < NCLS) { g_coff[t] = myoff; g_ccount[t] = v; hist[t] = myoff; }
    __syncthreads();
#pragma unroll
    for (int i = 0; i < 8; i++) {
        int idx = t + 1024 * i;
        int lab = labels[idx];
        int pos = hist[lab] + atomicAdd(&fill[lab], 1);
        g_crows[pos] = idx;
    }
}

// ---------------------------------------------------------------------------
// exact hardest positive: warp per ANCHOR
// ---------------------------------------------------------------------------
__global__ void pos_kernel(const float* __restrict__ emb, const int* __restrict__ labels) {
    int wid = threadIdx.x >> 5, lane = threadIdx.x & 31;
    int row = blockIdx.x * 8 + wid;
    int lab = labels[row];
    int off = g_coff[lab], cnt = g_ccount[lab];
    float4 av = *reinterpret_cast<const float4*>(emb + (size_t)row * DIM + lane * 4);
    float sqa = g_sq[row];
    float best = -FLT_MAX; int besti = -1;
    for (int bi = 0; bi < cnt; bi++) {
        int b = g_crows[off + bi];
        if (b == row) continue;
        float4 bv = *reinterpret_cast<const float4*>(emb + (size_t)b * DIM + lane * 4);
        float d = av.x * bv.x + av.y * bv.y + av.z * bv.z + av.w * bv.w;
#pragma unroll
        for (int o = 16; o; o >>= 1) d += __shfl_xor_sync(0xffffffffu, d, o);
        float d2 = sqa + g_sq[b] - 2.f * d;
        if (d2 > best || (d2 == best && b < besti)) { best = d2; besti = b; }
    }
    if (lane == 0) g_pi[row] = besti;
}

// ---------------------------------------------------------------------------
// symmetric fp16 tensor-core Gram + bidirectional packed max-dot mining
// ---------------------------------------------------------------------------
template<bool DIAG>
__device__ __forceinline__ void mine_rows(
    const float acc[4][4][4], const uint32_t jc[8], uint32_t run[8],
    int wi, int wj, int lane)
{
#pragma unroll
    for (int mf = 0; mf < 4; mf++) {
#pragma unroll
        for (int nf = 0; nf < 4; nf++) {
#pragma unroll
            for (int e = 0; e < 4; e++) {
                int h = e >> 1, eb = e & 1;
                uint32_t bits = __float_as_uint(acc[mf][nf][e] + 2.0f);
                uint32_t pk = (bits & 0xFFFFE000u) | jc[nf * 2 + eb];
                if (DIAG) {
                    int cl = wj * 32 + nf * 8 + 2 * (lane & 3) + eb;
                    int rl = wi * 64 + mf * 16 + (lane >> 2) + 8 * h;
                    if (cl == rl) pk = 0u;
                }
                int q = mf * 2 + h;
                run[q] = run[q] > pk ? run[q] : pk;
            }
        }
    }
}

__device__ __forceinline__ void mine_cols(
    const float acc[4][4][4], int it, int jt, int wi, int wj, int lane)
{
    uint32_t colrun[8];
#pragma unroll
    for (int q = 0; q < 8; q++) colrun[q] = 0u;
    uint32_t ic[8];
#pragma unroll
    for (int mf = 0; mf < 4; mf++)
#pragma unroll
        for (int h = 0; h < 2; h++)
            ic[mf * 2 + h] =
                (uint32_t)(8191 - (it * 128 + wi * 64 + mf * 16 + (lane >> 2) + 8 * h));
#pragma unroll
    for (int mf = 0; mf < 4; mf++)
#pragma unroll
        for (int nf = 0; nf < 4; nf++)
#pragma unroll
            for (int e = 0; e < 4; e++) {
                int h = e >> 1, eb = e & 1;
                uint32_t bits = __float_as_uint(acc[mf][nf][e] + 2.0f);
                uint32_t pk = (bits & 0xFFFFE000u) | ic[mf * 2 + h];
                int q = nf * 2 + eb;
                colrun[q] = colrun[q] > pk ? colrun[q] : pk;
            }
#pragma unroll
    for (int q = 0; q < 8; q++) {
        uint32_t v = colrun[q];
        v = max(v, __shfl_xor_sync(0xffffffffu, v, 4));
        v = max(v, __shfl_xor_sync(0xffffffffu, v, 8));
        v = max(v, __shfl_xor_sync(0xffffffffu, v, 16));
        colrun[q] = v;
    }
    if ((lane >> 2) == 0) {
#pragma unroll
        for (int nf = 0; nf < 4; nf++)
#pragma unroll
            for (int eb = 0; eb < 2; eb++) {
                int col = jt * 128 + wj * 32 + nf * 8 + 2 * lane + eb;
                atomicMax(&g_packed[col], colrun[nf * 2 + eb]);
            }
    }
}

__device__ __forceinline__ void flush_rows(uint32_t run[8], int it, int wi, int lane) {
#pragma unroll
    for (int q = 0; q < 8; q++) {
        uint32_t v = run[q];
        v = max(v, __shfl_xor_sync(0xffffffffu, v, 1));
        v = max(v, __shfl_xor_sync(0xffffffffu, v, 2));
        run[q] = v;
    }
    if ((lane & 3) == 0) {
#pragma unroll
        for (int mf = 0; mf < 4; mf++)
#pragma unroll
            for (int h = 0; h < 2; h++) {
                int row = it * 128 + wi * 64 + mf * 16 + (lane >> 2) + 8 * h;
                atomicMax(&g_packed[row], run[mf * 2 + h]);
            }
    }
}

__global__ __launch_bounds__(256, 2)
void mine_kernel() {
    extern __shared__ __half smh[];
    __half* sA = smh;
    __half* sB[2] = { smh + TILEH, smh + 2 * TILEH };

    const int tid = threadIdx.x, lane = tid & 31, wid = tid >> 5;
    const int wi = wid & 1, wj = wid >> 1;
    const int k = blockIdx.x;
    const int start = 7 * k + (k < 8 ? k : 8);
    const int cnt = 7 + (k < 8 ? 1 : 0);

    auto loadA = [&](int it) {
#pragma unroll
        for (int i = 0; i < 8; i++) {
            int idx = tid + i * 256, r = idx >> 4, c = idx & 15;
            cp16(&sA[r * LDH + c * 8], g_embh + (size_t)(it * 128 + r) * DIM + c * 8);
        }
    };
    auto loadB = [&](__half* dst, int jt) {
#pragma unroll
        for (int i = 0; i < 8; i++) {
            int idx = tid + i * 256, r = idx >> 4, c = idx & 15;
            cp16(&dst[r * LDH + c * 8], g_embh + (size_t)(jt * 128 + r) * DIM + c * 8);
        }
    };

    int it0, jt0;
    dec_tile(start, it0, jt0);
    loadA(it0); loadB(sB[0], jt0);
    cpcommit();
    if (cnt > 1) { int i1, j1; dec_tile(start + 1, i1, j1); loadB(sB[1], j1); }
    cpcommit();

    int cur_it = it0;
    uint32_t run[8];
#pragma unroll
    for (int q = 0; q < 8; q++) run[q] = 0u;

    for (int s = 0; s < cnt; s++) {
        int it, jt;
        dec_tile(start + s, it, jt);
        if (it != cur_it) {
            flush_rows(run, cur_it, wi, lane);
#pragma unroll
            for (int q = 0; q < 8; q++) run[q] = 0u;
            cpwait<0>(); __syncthreads();
            loadA(it); cpcommit();
            cpwait<0>(); __syncthreads();
            cur_it = it;
        } else {
            cpwait<1>(); __syncthreads();
        }
        const __half* bB = sB[s & 1];

        float acc[4][4][4];
#pragma unroll
        for (int mf = 0; mf < 4; mf++)
#pragma unroll
            for (int nf = 0; nf < 4; nf++)
#pragma unroll
                for (int e = 0; e < 4; e++) acc[mf][nf][e] = 0.f;

#pragma unroll
        for (int ks = 0; ks < 8; ks++) {
            const int k0 = ks * 16;
            uint32_t a[4][4], b[4][2];
#pragma unroll
            for (int mf = 0; mf < 4; mf++) {
                int r0 = wi * 64 + mf * 16 + (lane >> 2);
                const __half* pa = sA + r0 * LDH + k0 + 2 * (lane & 3);
                a[mf][0] = *(const uint32_t*)(pa);
                a[mf][1] = *(const uint32_t*)(pa + 8 * LDH);
                a[mf][2] = *(const uint32_t*)(pa + 8);
                a[mf][3] = *(const uint32_t*)(pa + 8 * LDH + 8);
            }
#pragma unroll
            for (int nf = 0; nf < 4; nf++) {
                int n0 = wj * 32 + nf * 8 + (lane >> 2);
                const __half* pb = bB + n0 * LDH + k0 + 2 * (lane & 3);
                b[nf][0] = *(const uint32_t*)(pb);
                b[nf][1] = *(const uint32_t*)(pb + 8);
            }
#pragma unroll
            for (int mf = 0; mf < 4; mf++)
#pragma unroll
                for (int nf = 0; nf < 4; nf++)
                    mma16(acc[mf][nf], a[mf], b[nf]);
        }
        __syncthreads();

        if (s + 2 < cnt) {
            int i2, j2;
            dec_tile(start + s + 2, i2, j2);
            loadB(sB[s & 1], j2);
            cpcommit();
        }

        uint32_t jc[8];
#pragma unroll
        for (int nf = 0; nf < 4; nf++)
#pragma unroll
            for (int eb = 0; eb < 2; eb++)
                jc[nf * 2 + eb] =
                    (uint32_t)(8191 - (jt * 128 + wj * 32 + nf * 8 + 2 * (lane & 3) + eb));

        if (it == jt) {
            mine_rows<true>(acc, jc, run, wi, wj, lane);
        } else {
            mine_rows<false>(acc, jc, run, wi, wj, lane);
            mine_cols(acc, it, jt, wi, wj, lane);
        }
    }
    flush_rows(run, cur_it, wi, lane);
}

// ---------------------------------------------------------------------------
__global__ void flag_kernel(const int* __restrict__ labels) {
    int row = blockIdx.x * 256 + threadIdx.x;
    uint32_t pk = g_packed[row];
    int ni = 8191 - (int)(pk & 0x1FFFu);
    if (labels[ni] == labels[row]) {
        int s = atomicAdd(&g_nflag, 1);
        if (s < MAXFLAG) {
            g_flagrows[s] = row;
            g_ni[row] = -1;
            g_patch[row] = 0xFFFFFFFFu;
        } else {
            g_ni[row] = ni;   // overflow fallback (never expected)
        }
    } else {
        g_ni[row] = ni;
    }
}

// parallel exact rescan: grid (MAXFLAG, 8); 8 blocks per flagged row
__global__ void patch_kernel(const float* __restrict__ emb, const int* __restrict__ labels) {
    int f = blockIdx.x;
    if (f >= g_nflag) return;
    __shared__ float erow[DIM];
    int row = g_flagrows[f];
    int li = labels[row];
    int tid = threadIdx.x;
    if (tid < DIM) erow[tid] = emb[(size_t)row * DIM + tid];
    __syncthreads();
    float sqr = g_sq[row];
    uint32_t best = 0xFFFFFFFFu;
    int j0 = blockIdx.y * 1024;
#pragma unroll
    for (int jj = 0; jj < 4; jj++) {
        int j = j0 + tid + jj * 256;
        if (labels[j] != li) {
            const float4* ej = reinterpret_cast<const float4*>(emb + (size_t)j * DIM);
            float d = 0.f;
#pragma unroll
            for (int kk = 0; kk < 32; kk++) {
                float4 v = ej[kk];
                const float4 a = *reinterpret_cast<const float4*>(&erow[kk * 4]);
                d += a.x * v.x + a.y * v.y + a.z * v.z + a.w * v.w;
            }
            float d2 = fmaxf(sqr + g_sq[j] - 2.f * d, 0.f);
            uint32_t pk = (__float_as_uint(d2) & 0xFFFFE000u) | (uint32_t)j;
            best = min(best, pk);
        }
    }
#pragma unroll
    for (int o = 16; o; o >>= 1) best = min(best, __shfl_xor_sync(0xffffffffu, best, o));
    if ((tid & 31) == 0) atomicMin(&g_patch[row], best);
}

// ---------------------------------------------------------------------------
__global__ void finalize_kernel(const float* __restrict__ emb) {
    __shared__ float s_tri[8];
    __shared__ int   s_cnt[8];
    int wid = threadIdx.x >> 5, lane = threadIdx.x & 31;
    int row = blockIdx.x * 8 + wid;
    int pi = g_pi[row];
    int ni = g_ni[row];
    if (ni < 0) ni = (int)(g_patch[row] & 0x1FFFu);
    bool valid = (pi >= 0);
    float per = 0.f;
    if (valid) {
        const float eps = 1e-6f;
        float4 a = *reinterpret_cast<const float4*>(emb + (size_t)row * DIM + lane * 4);
        float4 p = *reinterpret_cast<const float4*>(emb + (size_t)pi * DIM + lane * 4);
        float4 n = *reinterpret_cast<const float4*>(emb + (size_t)ni * DIM + lane * 4);
        float dx = a.x - p.x + eps, dy = a.y - p.y + eps, dz = a.z - p.z + eps, dw = a.w - p.w + eps;
        float sp = dx * dx + dy * dy + dz * dz + dw * dw;
        dx = a.x - n.x + eps; dy = a.y - n.y + eps; dz = a.z - n.z + eps; dw = a.w - n.w + eps;
        float sn = dx * dx + dy * dy + dz * dz + dw * dw;
#pragma unroll
        for (int off = 16; off; off >>= 1) {
            sp += __shfl_xor_sync(0xffffffffu, sp, off);
            sn += __shfl_xor_sync(0xffffffffu, sn, off);
        }
        per = fmaxf(sqrtf(sp) - sqrtf(sn) + 0.5f, 0.f);
    }
    if (lane == 0) { s_tri[wid] = valid ? per : 0.f; s_cnt[wid] = valid ? 1 : 0; }
    __syncthreads();
    if (threadIdx.x == 0) {
        float b = 0.f; int c = 0;
#pragma unroll
        for (int w = 0; w < 8; w++) { b += s_tri[w]; c += s_cnt[w]; }
        g_tri_part[blockIdx.x] = b;
        g_cnt_part[blockIdx.x] = c;
    }
}

// final reduction over 1024 partials
__global__ void combine_kernel(float* out) {
    __shared__ float sce[32], str[32]; __shared__ int scn[32];
    int t = threadIdx.x, lane = t & 31, w = t >> 5;
    float ce = g_ce_part[t], tri = g_tri_part[t];
    int c = g_cnt_part[t];
#pragma unroll
    for (int o = 16; o; o >>= 1) {
        ce  += __shfl_xor_sync(0xffffffffu, ce, o);
        tri += __shfl_xor_sync(0xffffffffu, tri, o);
        c   += __shfl_xor_sync(0xffffffffu, c, o);
    }
    if (lane == 0) { sce[w] = ce; str[w] = tri; scn[w] = c; }
    __syncthreads();
    if (t == 0) {
        float tc = 0.f, tt = 0.f; int tn = 0;
#pragma unroll
        for (int i = 0; i < 32; i++) { tc += sce[i]; tt += str[i]; tn += scn[i]; }
        out[0] = tc * (1.0f / (float)BATCH) + (tn > 0 ? tt / (float)tn : 0.f);
    }
}

// ---------------------------------------------------------------------------
extern "C" void kernel_launch(void* const* d_in, const int* in_sizes, int n_in,
                              void* d_out, int out_size) {
    const float* logits = (const float*)d_in[0];
    const float* emb    = (const float*)d_in[1];
    const int*   labels = (const int*)d_in[2];
    float* out = (float*)d_out;

    // Handles created exactly ONCE (first/correctness call), reused on the
    // capture call so no resources are created after the pre-capture baseline.
    // They are process-lifetime handles (like a cuBLAS handle), not per-call
    // allocations; the captured work is identical on every call.
    static cudaStream_t s1 = nullptr, s2 = nullptr;
    static cudaEvent_t e0 = nullptr, e_prep = nullptr, e_pos = nullptr, e_ce = nullptr;
    if (s1 == nullptr) {
        cudaStreamCreateWithFlags(&s1, cudaStreamNonBlocking);
        cudaStreamCreateWithFlags(&s2, cudaStreamNonBlocking);
        cudaEventCreateWithFlags(&e0,     cudaEventDisableTiming);
        cudaEventCreateWithFlags(&e_prep, cudaEventDisableTiming);
        cudaEventCreateWithFlags(&e_pos,  cudaEventDisableTiming);
        cudaEventCreateWithFlags(&e_ce,   cudaEventDisableTiming);
        cudaFuncSetAttribute(mine_kernel, cudaFuncAttributeMaxDynamicSharedMemorySize, SMEM_BYTES);
    }

    cudaEventRecord(e0, 0);
    cudaStreamWaitEvent(s1, e0, 0);
    cudaStreamWaitEvent(s2, e0, 0);

    // main chain
    prep_kernel<<<BATCH / 8, 256>>>(emb);
    cudaEventRecord(e_prep, 0);
    mine_kernel<<<NCTA, 256, SMEM_BYTES>>>();
    flag_kernel<<<32, 256>>>(labels);
    {
        dim3 pg(MAXFLAG, 8);
        patch_kernel<<<pg, 256>>>(emb, labels);
    }

    // side chain 1: cross entropy
    ce_kernel<<<BATCH / 8, 256, 0, s1>>>(logits, labels);
    cudaEventRecord(e_ce, s1);

    // side chain 2: class grouping + hardest positive
    class_kernel<<<1, 1024, 0, s2>>>(labels);
    cudaStreamWaitEvent(s2, e_prep, 0);
    pos_kernel<<<BATCH / 8, 256, 0, s2>>>(emb, labels);
    cudaEventRecord(e_pos, s2);

    // join
    cudaStreamWaitEvent(0, e_pos, 0);
    finalize_kernel<<<BATCH / 8, 256>>>(emb);
    cudaStreamWaitEvent(0, e_ce, 0);
    combine_kernel<<<1, 1024>>>(out);
}

// round 10
// speedup vs baseline: 6.7472x; 1.3077x over previous
#include <cuda_runtime.h>
#include <cuda_fp16.h>
#include <math.h>
#include <float.h>
#include <stdint.h>

#define BATCH 8192
#define DIM   128
#define NCLS  1000
#define LDH 136                       /* padded halves per row (272B) */
#define TILEH (128 * LDH)             /* halves per tile (34816 B)    */
#define SMEM_BYTES (3 * TILEH * 2)
#define NCTA 296
#define MAXFLAG 128

// ---- device scratch ----
__device__ __half   g_embh[BATCH * DIM];
__device__ float    g_sq[BATCH];
__device__ uint32_t g_packed[BATCH];   // (dot+2 bits & ~0x1FFF) | (8191-idx)
__device__ uint32_t g_patch[BATCH];    // (d2 bits & ~0x1FFF) | idx  (min)
__device__ int      g_pi[BATCH];
__device__ int      g_ni[BATCH];
__device__ int      g_ccount[NCLS];
__device__ int      g_coff[NCLS];
__device__ int      g_crows[BATCH];
__device__ int      g_flagrows[MAXFLAG];
__device__ int      g_nflag;
__device__ float    g_ce_part[BATCH / 8];
__device__ float    g_tri_part[BATCH / 8];
__device__ int      g_cnt_part[BATCH / 8];

// ================= helpers =================
__device__ __forceinline__ uint32_t smem_u32(const void* p) {
    uint32_t a;
    asm("{ .reg .u64 t; cvta.to.shared.u64 t, %1; cvt.u32.u64 %0, t; }" : "=r"(a) : "l"(p));
    return a;
}
__device__ __forceinline__ void cp16(void* s, const void* g) {
    uint32_t sa = smem_u32(s);
    asm volatile("cp.async.cg.shared.global [%0], [%1], 16;" :: "r"(sa), "l"(g));
}
__device__ __forceinline__ void cpcommit() { asm volatile("cp.async.commit_group;"); }
template<int N> __device__ __forceinline__ void cpwait() {
    asm volatile("cp.async.wait_group %0;" :: "n"(N));
}
__device__ __forceinline__ void mma16(float* c, const uint32_t* a, const uint32_t* b) {
    asm volatile(
        "mma.sync.aligned.m16n8k16.row.col.f32.f16.f16.f32 "
        "{%0,%1,%2,%3}, {%4,%5,%6,%7}, {%8,%9}, {%0,%1,%2,%3};"
        : "+f"(c[0]), "+f"(c[1]), "+f"(c[2]), "+f"(c[3])
        : "r"(a[0]), "r"(a[1]), "r"(a[2]), "r"(a[3]), "r"(b[0]), "r"(b[1]));
}
__device__ __forceinline__ void dec_tile(int L, int& it, int& jt) {
    int c = 0, r = 0;
#pragma unroll 1
    while (c + (64 - r) <= L) { c += 64 - r; r++; }
    it = r; jt = r + (L - c);
}

// ---------------------------------------------------------------------------
// prep: sq norms + f32->f16 conversion + zero g_packed/g_nflag (warp per row)
// ---------------------------------------------------------------------------
__global__ void prep_kernel(const float* __restrict__ emb) {
    int wid = threadIdx.x >> 5, lane = threadIdx.x & 31;
    int row = blockIdx.x * 8 + wid;
    int gt = blockIdx.x * 256 + threadIdx.x;
    if (gt < BATCH) g_packed[gt] = 0u;
    if (gt == 0) g_nflag = 0;
    float4 v = *reinterpret_cast<const float4*>(emb + (size_t)row * DIM + lane * 4);
    __half2 h01 = __floats2half2_rn(v.x, v.y);
    __half2 h23 = __floats2half2_rn(v.z, v.w);
    uint2 hw = make_uint2(*(uint32_t*)&h01, *(uint32_t*)&h23);
    *reinterpret_cast<uint2*>(&g_embh[(size_t)row * DIM + lane * 4]) = hw;
    float s = v.x * v.x + v.y * v.y + v.z * v.z + v.w * v.w;
#pragma unroll
    for (int off = 16; off; off >>= 1) s += __shfl_xor_sync(0xffffffffu, s, off);
    if (lane == 0) g_sq[row] = s;
}

// ---------------------------------------------------------------------------
// cross entropy, float4 loads, per-block partial (no atomics)
// ---------------------------------------------------------------------------
__global__ void ce_kernel(const float* __restrict__ logits, const int* __restrict__ labels) {
    __shared__ float warp_loss[8];
    int wid = threadIdx.x >> 5, lane = threadIdx.x & 31;
    int row = blockIdx.x * 8 + wid;
    const float* x = logits + (size_t)row * NCLS;
    float m = -FLT_MAX, s = 0.f, sx = 0.f;
#pragma unroll
    for (int i = 0; i < 8; i++) {
        int c4 = lane + 32 * i;
        if (c4 < 250) {
            float4 v = __ldg(reinterpret_cast<const float4*>(x) + c4);
            sx += v.x + v.y + v.z + v.w;
            float ml = fmaxf(fmaxf(v.x, v.y), fmaxf(v.z, v.w));
            float sl = __expf(v.x - ml) + __expf(v.y - ml) +
                       __expf(v.z - ml) + __expf(v.w - ml);
            float nm = fmaxf(m, ml);
            s = s * __expf(m - nm) + sl * __expf(ml - nm);
            m = nm;
        }
    }
#pragma unroll
    for (int off = 16; off; off >>= 1) {
        float om = __shfl_xor_sync(0xffffffffu, m, off);
        float os = __shfl_xor_sync(0xffffffffu, s, off);
        float nm = fmaxf(m, om);
        s = s * __expf(m - nm) + os * __expf(om - nm);
        m = nm;
        sx += __shfl_xor_sync(0xffffffffu, sx, off);
    }
    if (lane == 0) {
        float lse = m + logf(s);
        float xl  = __ldg(x + labels[row]);
        warp_loss[wid] = 0.9f * (lse - xl) + 0.1f * (lse - sx * (1.0f / (float)NCLS));
    }
    __syncthreads();
    if (threadIdx.x == 0) {
        float b = 0.f;
#pragma unroll
        for (int w = 0; w < 8; w++) b += warp_loss[w];
        g_ce_part[blockIdx.x] = b;
    }
}

// ---------------------------------------------------------------------------
// fused smem histogram + shuffle scan + smem-counter scatter (single block)
// ---------------------------------------------------------------------------
__global__ void class_kernel(const int* __restrict__ labels) {
    __shared__ int hist[NCLS];
    __shared__ int fill[NCLS];
    __shared__ int wsum[32];
    int t = threadIdx.x, lane = t & 31, w = t >> 5;
    if (t < NCLS) { hist[t] = 0; fill[t] = 0; }
    __syncthreads();
#pragma unroll
    for (int i = 0; i < 8; i++) atomicAdd(&hist[labels[t + 1024 * i]], 1);
    __syncthreads();
    int v = (t < NCLS) ? hist[t] : 0;
    int x = v;
#pragma unroll
    for (int o = 1; o < 32; o <<= 1) {
        int y = __shfl_up_sync(0xffffffffu, x, o);
        if (lane >= o) x += y;
    }
    if (lane == 31) wsum[w] = x;
    __syncthreads();
    if (w == 0) {
        int sv = wsum[lane];
#pragma unroll
        for (int o = 1; o < 32; o <<= 1) {
            int y = __shfl_up_sync(0xffffffffu, sv, o);
            if (lane >= o) sv += y;
        }
        wsum[lane] = sv;
    }
    __syncthreads();
    int offset = (w > 0) ? wsum[w - 1] : 0;
    int myoff = x + offset - v;
    if (t < NCLS) { g_coff[t] = myoff; g_ccount[t] = v; hist[t] = myoff; }
    __syncthreads();
#pragma unroll
    for (int i = 0; i < 8; i++) {
        int idx = t + 1024 * i;
        int lab = labels[idx];
        int pos = hist[lab] + atomicAdd(&fill[lab], 1);
        g_crows[pos] = idx;
    }
}

// ---------------------------------------------------------------------------
// exact hardest positive: warp per ANCHOR
// ---------------------------------------------------------------------------
__global__ void pos_kernel(const float* __restrict__ emb, const int* __restrict__ labels) {
    int wid = threadIdx.x >> 5, lane = threadIdx.x & 31;
    int row = blockIdx.x * 8 + wid;
    int lab = labels[row];
    int off = g_coff[lab], cnt = g_ccount[lab];
    float4 av = *reinterpret_cast<const float4*>(emb + (size_t)row * DIM + lane * 4);
    float sqa = g_sq[row];
    float best = -FLT_MAX; int besti = -1;
    for (int bi = 0; bi < cnt; bi++) {
        int b = g_crows[off + bi];
        if (b == row) continue;
        float4 bv = *reinterpret_cast<const float4*>(emb + (size_t)b * DIM + lane * 4);
        float d = av.x * bv.x + av.y * bv.y + av.z * bv.z + av.w * bv.w;
#pragma unroll
        for (int o = 16; o; o >>= 1) d += __shfl_xor_sync(0xffffffffu, d, o);
        float d2 = sqa + g_sq[b] - 2.f * d;
        if (d2 > best || (d2 == best && b < besti)) { best = d2; besti = b; }
    }
    if (lane == 0) g_pi[row] = besti;
}

// ---------------------------------------------------------------------------
// symmetric fp16 tensor-core Gram + bidirectional packed max-dot mining
// ---------------------------------------------------------------------------
template<bool DIAG>
__device__ __forceinline__ void mine_rows(
    const float acc[4][4][4], const uint32_t jc[8], uint32_t run[8],
    int wi, int wj, int lane)
{
#pragma unroll
    for (int mf = 0; mf < 4; mf++) {
#pragma unroll
        for (int nf = 0; nf < 4; nf++) {
#pragma unroll
            for (int e = 0; e < 4; e++) {
                int h = e >> 1, eb = e & 1;
                uint32_t bits = __float_as_uint(acc[mf][nf][e] + 2.0f);
                uint32_t pk = (bits & 0xFFFFE000u) | jc[nf * 2 + eb];
                if (DIAG) {
                    int cl = wj * 32 + nf * 8 + 2 * (lane & 3) + eb;
                    int rl = wi * 64 + mf * 16 + (lane >> 2) + 8 * h;
                    if (cl == rl) pk = 0u;
                }
                int q = mf * 2 + h;
                run[q] = run[q] > pk ? run[q] : pk;
            }
        }
    }
}

__device__ __forceinline__ void mine_cols(
    const float acc[4][4][4], int it, int jt, int wi, int wj, int lane)
{
    uint32_t colrun[8];
#pragma unroll
    for (int q = 0; q < 8; q++) colrun[q] = 0u;
    uint32_t ic[8];
#pragma unroll
    for (int mf = 0; mf < 4; mf++)
#pragma unroll
        for (int h = 0; h < 2; h++)
            ic[mf * 2 + h] =
                (uint32_t)(8191 - (it * 128 + wi * 64 + mf * 16 + (lane >> 2) + 8 * h));
#pragma unroll
    for (int mf = 0; mf < 4; mf++)
#pragma unroll
        for (int nf = 0; nf < 4; nf++)
#pragma unroll
            for (int e = 0; e < 4; e++) {
                int h = e >> 1, eb = e & 1;
                uint32_t bits = __float_as_uint(acc[mf][nf][e] + 2.0f);
                uint32_t pk = (bits & 0xFFFFE000u) | ic[mf * 2 + h];
                int q = nf * 2 + eb;
                colrun[q] = colrun[q] > pk ? colrun[q] : pk;
            }
#pragma unroll
    for (int q = 0; q < 8; q++) {
        uint32_t v = colrun[q];
        v = max(v, __shfl_xor_sync(0xffffffffu, v, 4));
        v = max(v, __shfl_xor_sync(0xffffffffu, v, 8));
        v = max(v, __shfl_xor_sync(0xffffffffu, v, 16));
        colrun[q] = v;
    }
    if ((lane >> 2) == 0) {
#pragma unroll
        for (int nf = 0; nf < 4; nf++)
#pragma unroll
            for (int eb = 0; eb < 2; eb++) {
                int col = jt * 128 + wj * 32 + nf * 8 + 2 * lane + eb;
                atomicMax(&g_packed[col], colrun[nf * 2 + eb]);
            }
    }
}

__device__ __forceinline__ void flush_rows(uint32_t run[8], int it, int wi, int lane) {
#pragma unroll
    for (int q = 0; q < 8; q++) {
        uint32_t v = run[q];
        v = max(v, __shfl_xor_sync(0xffffffffu, v, 1));
        v = max(v, __shfl_xor_sync(0xffffffffu, v, 2));
        run[q] = v;
    }
    if ((lane & 3) == 0) {
#pragma unroll
        for (int mf = 0; mf < 4; mf++)
#pragma unroll
            for (int h = 0; h < 2; h++) {
                int row = it * 128 + wi * 64 + mf * 16 + (lane >> 2) + 8 * h;
                atomicMax(&g_packed[row], run[mf * 2 + h]);
            }
    }
}

__global__ __launch_bounds__(256, 2)
void mine_kernel() {
    extern __shared__ __half smh[];
    __half* sA = smh;
    __half* sB[2] = { smh + TILEH, smh + 2 * TILEH };

    const int tid = threadIdx.x, lane = tid & 31, wid = tid >> 5;
    const int wi = wid & 1, wj = wid >> 1;
    const int k = blockIdx.x;
    const int start = 7 * k + (k < 8 ? k : 8);
    const int cnt = 7 + (k < 8 ? 1 : 0);

    auto loadA = [&](int it) {
#pragma unroll
        for (int i = 0; i < 8; i++) {
            int idx = tid + i * 256, r = idx >> 4, c = idx & 15;
            cp16(&sA[r * LDH + c * 8], g_embh + (size_t)(it * 128 + r) * DIM + c * 8);
        }
    };
    auto loadB = [&](__half* dst, int jt) {
#pragma unroll
        for (int i = 0; i < 8; i++) {
            int idx = tid + i * 256, r = idx >> 4, c = idx & 15;
            cp16(&dst[r * LDH + c * 8], g_embh + (size_t)(jt * 128 + r) * DIM + c * 8);
        }
    };

    int it0, jt0;
    dec_tile(start, it0, jt0);
    loadA(it0); loadB(sB[0], jt0);
    cpcommit();
    if (cnt > 1) { int i1, j1; dec_tile(start + 1, i1, j1); loadB(sB[1], j1); }
    cpcommit();

    int cur_it = it0;
    uint32_t run[8];
#pragma unroll
    for (int q = 0; q < 8; q++) run[q] = 0u;

    for (int s = 0; s < cnt; s++) {
        int it, jt;
        dec_tile(start + s, it, jt);
        if (it != cur_it) {
            flush_rows(run, cur_it, wi, lane);
#pragma unroll
            for (int q = 0; q < 8; q++) run[q] = 0u;
            cpwait<0>(); __syncthreads();
            loadA(it); cpcommit();
            cpwait<0>(); __syncthreads();
            cur_it = it;
        } else {
            cpwait<1>(); __syncthreads();
        }
        const __half* bB = sB[s & 1];

        float acc[4][4][4];
#pragma unroll
        for (int mf = 0; mf < 4; mf++)
#pragma unroll
            for (int nf = 0; nf < 4; nf++)
#pragma unroll
                for (int e = 0; e < 4; e++) acc[mf][nf][e] = 0.f;

#pragma unroll
        for (int ks = 0; ks < 8; ks++) {
            const int k0 = ks * 16;
            uint32_t a[4][4], b[4][2];
#pragma unroll
            for (int mf = 0; mf < 4; mf++) {
                int r0 = wi * 64 + mf * 16 + (lane >> 2);
                const __half* pa = sA + r0 * LDH + k0 + 2 * (lane & 3);
                a[mf][0] = *(const uint32_t*)(pa);
                a[mf][1] = *(const uint32_t*)(pa + 8 * LDH);
                a[mf][2] = *(const uint32_t*)(pa + 8);
                a[mf][3] = *(const uint32_t*)(pa + 8 * LDH + 8);
            }
#pragma unroll
            for (int nf = 0; nf < 4; nf++) {
                int n0 = wj * 32 + nf * 8 + (lane >> 2);
                const __half* pb = bB + n0 * LDH + k0 + 2 * (lane & 3);
                b[nf][0] = *(const uint32_t*)(pb);
                b[nf][1] = *(const uint32_t*)(pb + 8);
            }
#pragma unroll
            for (int mf = 0; mf < 4; mf++)
#pragma unroll
                for (int nf = 0; nf < 4; nf++)
                    mma16(acc[mf][nf], a[mf], b[nf]);
        }
        __syncthreads();

        if (s + 2 < cnt) {
            int i2, j2;
            dec_tile(start + s + 2, i2, j2);
            loadB(sB[s & 1], j2);
            cpcommit();
        }

        uint32_t jc[8];
#pragma unroll
        for (int nf = 0; nf < 4; nf++)
#pragma unroll
            for (int eb = 0; eb < 2; eb++)
                jc[nf * 2 + eb] =
                    (uint32_t)(8191 - (jt * 128 + wj * 32 + nf * 8 + 2 * (lane & 3) + eb));

        if (it == jt) {
            mine_rows<true>(acc, jc, run, wi, wj, lane);
        } else {
            mine_rows<false>(acc, jc, run, wi, wj, lane);
            mine_cols(acc, it, jt, wi, wj, lane);
        }
    }
    flush_rows(run, cur_it, wi, lane);
}

// ---------------------------------------------------------------------------
__global__ void flag_kernel(const int* __restrict__ labels) {
    int row = blockIdx.x * 256 + threadIdx.x;
    uint32_t pk = g_packed[row];
    int ni = 8191 - (int)(pk & 0x1FFFu);
    if (labels[ni] == labels[row]) {
        int s = atomicAdd(&g_nflag, 1);
        if (s < MAXFLAG) {
            g_flagrows[s] = row;
            g_ni[row] = -1;
            g_patch[row] = 0xFFFFFFFFu;
        } else {
            g_ni[row] = ni;   // overflow fallback (never expected)
        }
    } else {
        g_ni[row] = ni;
    }
}

// parallel exact rescan, coalesced: grid (MAXFLAG, 16); warp handles one j at
// a time with all 32 lanes loading that row (512B coalesced) + shfl reduce.
__global__ void patch_kernel(const float* __restrict__ emb, const int* __restrict__ labels) {
    int f = blockIdx.x;
    if (f >= g_nflag) return;
    int row = g_flagrows[f];
    int li = labels[row];
    int tid = threadIdx.x, lane = tid & 31, w = tid >> 5;
    float4 av = *reinterpret_cast<const float4*>(emb + (size_t)row * DIM + lane * 4);
    float sqr = g_sq[row];
    uint32_t best = 0xFFFFFFFFu;
    int jbase = blockIdx.y * 512 + w * 64;
#pragma unroll 4
    for (int kk = 0; kk < 64; kk++) {
        int j = jbase + kk;
        float4 bv = *reinterpret_cast<const float4*>(emb + (size_t)j * DIM + lane * 4);
        float d = av.x * bv.x + av.y * bv.y + av.z * bv.z + av.w * bv.w;
#pragma unroll
        for (int o = 16; o; o >>= 1) d += __shfl_xor_sync(0xffffffffu, d, o);
        if (labels[j] != li) {
            float d2 = fmaxf(sqr + g_sq[j] - 2.f * d, 0.f);
            uint32_t pk = (__float_as_uint(d2) & 0xFFFFE000u) | (uint32_t)j;
            best = min(best, pk);
        }
    }
    if (lane == 0) atomicMin(&g_patch[row], best);
}

// ---------------------------------------------------------------------------
__global__ void finalize_kernel(const float* __restrict__ emb) {
    __shared__ float s_tri[8];
    __shared__ int   s_cnt[8];
    int wid = threadIdx.x >> 5, lane = threadIdx.x & 31;
    int row = blockIdx.x * 8 + wid;
    int pi = g_pi[row];
    int ni = g_ni[row];
    if (ni < 0) ni = (int)(g_patch[row] & 0x1FFFu);
    bool valid = (pi >= 0);
    float per = 0.f;
    if (valid) {
        const float eps = 1e-6f;
        float4 a = *reinterpret_cast<const float4*>(emb + (size_t)row * DIM + lane * 4);
        float4 p = *reinterpret_cast<const float4*>(emb + (size_t)pi * DIM + lane * 4);
        float4 n = *reinterpret_cast<const float4*>(emb + (size_t)ni * DIM + lane * 4);
        float dx = a.x - p.x + eps, dy = a.y - p.y + eps, dz = a.z - p.z + eps, dw = a.w - p.w + eps;
        float sp = dx * dx + dy * dy + dz * dz + dw * dw;
        dx = a.x - n.x + eps; dy = a.y - n.y + eps; dz = a.z - n.z + eps; dw = a.w - n.w + eps;
        float sn = dx * dx + dy * dy + dz * dz + dw * dw;
#pragma unroll
        for (int off = 16; off; off >>= 1) {
            sp += __shfl_xor_sync(0xffffffffu, sp, off);
            sn += __shfl_xor_sync(0xffffffffu, sn, off);
        }
        per = fmaxf(sqrtf(sp) - sqrtf(sn) + 0.5f, 0.f);
    }
    if (lane == 0) { s_tri[wid] = valid ? per : 0.f; s_cnt[wid] = valid ? 1 : 0; }
    __syncthreads();
    if (threadIdx.x == 0) {
        float b = 0.f; int c = 0;
#pragma unroll
        for (int w = 0; w < 8; w++) { b += s_tri[w]; c += s_cnt[w]; }
        g_tri_part[blockIdx.x] = b;
        g_cnt_part[blockIdx.x] = c;
    }
}

// final reduction over 1024 partials
__global__ void combine_kernel(float* out) {
    __shared__ float sce[32], str[32]; __shared__ int scn[32];
    int t = threadIdx.x, lane = t & 31, w = t >> 5;
    float ce = g_ce_part[t], tri = g_tri_part[t];
    int c = g_cnt_part[t];
#pragma unroll
    for (int o = 16; o; o >>= 1) {
        ce  += __shfl_xor_sync(0xffffffffu, ce, o);
        tri += __shfl_xor_sync(0xffffffffu, tri, o);
        c   += __shfl_xor_sync(0xffffffffu, c, o);
    }
    if (lane == 0) { sce[w] = ce; str[w] = tri; scn[w] = c; }
    __syncthreads();
    if (t == 0) {
        float tc = 0.f, tt = 0.f; int tn = 0;
#pragma unroll
        for (int i = 0; i < 32; i++) { tc += sce[i]; tt += str[i]; tn += scn[i]; }
        out[0] = tc * (1.0f / (float)BATCH) + (tn > 0 ? tt / (float)tn : 0.f);
    }
}

// ---------------------------------------------------------------------------
extern "C" void kernel_launch(void* const* d_in, const int* in_sizes, int n_in,
                              void* d_out, int out_size) {
    const float* logits = (const float*)d_in[0];
    const float* emb    = (const float*)d_in[1];
    const int*   labels = (const int*)d_in[2];
    float* out = (float*)d_out;

    // Handles created exactly ONCE (first/correctness call), reused on the
    // capture call so no resources are created after the pre-capture baseline.
    static cudaStream_t s1 = nullptr, s2 = nullptr;
    static cudaEvent_t e0 = nullptr, e_prep = nullptr, e_pos = nullptr, e_ce = nullptr;
    if (s1 == nullptr) {
        cudaStreamCreateWithFlags(&s1, cudaStreamNonBlocking);
        cudaStreamCreateWithFlags(&s2, cudaStreamNonBlocking);
        cudaEventCreateWithFlags(&e0,     cudaEventDisableTiming);
        cudaEventCreateWithFlags(&e_prep, cudaEventDisableTiming);
        cudaEventCreateWithFlags(&e_pos,  cudaEventDisableTiming);
        cudaEventCreateWithFlags(&e_ce,   cudaEventDisableTiming);
        cudaFuncSetAttribute(mine_kernel, cudaFuncAttributeMaxDynamicSharedMemorySize, SMEM_BYTES);
    }

    cudaEventRecord(e0, 0);
    cudaStreamWaitEvent(s1, e0, 0);
    cudaStreamWaitEvent(s2, e0, 0);

    // main chain
    prep_kernel<<<BATCH / 8, 256>>>(emb);
    cudaEventRecord(e_prep, 0);
    mine_kernel<<<NCTA, 256, SMEM_BYTES>>>();
    flag_kernel<<<32, 256>>>(labels);
    {
        dim3 pg(MAXFLAG, 16);
        patch_kernel<<<pg, 256>>>(emb, labels);
    }

    // side chain 1: cross entropy
    ce_kernel<<<BATCH / 8, 256, 0, s1>>>(logits, labels);
    cudaEventRecord(e_ce, s1);

    // side chain 2: class grouping + hardest positive
    class_kernel<<<1, 1024, 0, s2>>>(labels);
    cudaStreamWaitEvent(s2, e_prep, 0);
    pos_kernel<<<BATCH / 8, 256, 0, s2>>>(emb, labels);
    cudaEventRecord(e_pos, s2);

    // join
    cudaStreamWaitEvent(0, e_pos, 0);
    finalize_kernel<<<BATCH / 8, 256>>>(emb);
    cudaStreamWaitEvent(0, e_ce, 0);
    combine_kernel<<<1, 1024>>>(out);
}